// round 2
// baseline (speedup 1.0000x reference)
#include <cuda_runtime.h>
#include <math.h>

#define Bz 8
#define NC 2
#define NS 8
#define Cc 64
#define Hh 192
#define Ww 192
#define HW (Hh*Ww)

// ---- scratch (static __device__, no allocations) ----
__device__ float d_space[Bz*NC*NS*HW];   // raw sigmoid space planes [b][c][s][hw]
__device__ float d_planeSum[Bz*NC*NS];   // per-plane spatial sums
__device__ float d_g[Bz*16*9*64];        // [b][cs(16)][shift(9)][i(64)]
__device__ float d_tok2[Bz*NC*Cc];       // [b][c][d]
__device__ float d_Weff[Bz*NC*Cc*9];     // [b][c][o][k]
__device__ float d_F[Bz*NC*HW];          // attention-combined scalar map
__device__ double d_stat[2*Cc];          // per-channel sum, sumsq of y
__device__ float d_alpha[Cc];
__device__ float d_beta2[Cc];

__device__ __forceinline__ float sigmf(float v) {
    return 1.0f / (1.0f + __expf(-v));
}

// ---------------- K0: zero accumulators ----------------
__global__ void k_zero() {
    int i = blockIdx.x * blockDim.x + threadIdx.x;
    if (i < Bz*16*9*64) d_g[i] = 0.f;
    if (i < Bz*NC*NS) d_planeSum[i] = 0.f;
    if (i < Bz*NC*Cc) d_tok2[i] = 0.f;
    if (i < 2*Cc) d_stat[i] = 0.0;
}

// ---------------- K1: space planes + plane sums ----------------
// grid (12,12,16 planes), block 256
__global__ void __launch_bounds__(256) k_space(const float* __restrict__ cls,
                                               const float* __restrict__ Wc) {
    __shared__ float halo[18*18];
    __shared__ float wsm[63];
    __shared__ float bsum[8];
    int bc = blockIdx.z;
    int h0 = blockIdx.y * 16, w0 = blockIdx.x * 16;
    int tid = threadIdx.x;
    if (tid < 63) wsm[tid] = Wc[tid];
    if (tid < 8) bsum[tid] = 0.f;
    for (int idx = tid; idx < 324; idx += 256) {
        int r = idx / 18, cc = idx % 18;
        int gh = h0 - 1 + r, gw = w0 - 1 + cc;
        float v = 0.f;
        if (gh >= 0 && gh < Hh && gw >= 0 && gw < Ww)
            v = sigmf(cls[bc*HW + gh*Ww + gw]);
        halo[idx] = v;
    }
    __syncthreads();
    int py = tid >> 4, px = tid & 15;
    float vals[8];
    vals[0] = halo[(py+1)*18 + px + 1];
#pragma unroll
    for (int oc = 0; oc < 7; oc++) {
        float a = 0.f;
#pragma unroll
        for (int ky = 0; ky < 3; ky++)
#pragma unroll
            for (int kx = 0; kx < 3; kx++)
                a = fmaf(halo[(py+ky)*18 + px + kx], wsm[oc*9 + ky*3 + kx], a);
        vals[oc+1] = sigmf(a);
    }
    int pix = (h0 + py) * Ww + (w0 + px);
#pragma unroll
    for (int s = 0; s < 8; s++)
        d_space[(bc*8 + s)*HW + pix] = vals[s];
    // plane-sum reduction
#pragma unroll
    for (int s = 0; s < 8; s++) {
        float r = vals[s];
#pragma unroll
        for (int off = 16; off > 0; off >>= 1)
            r += __shfl_xor_sync(0xffffffffu, r, off);
        if ((tid & 31) == 0) atomicAdd(&bsum[s], r);
    }
    __syncthreads();
    if (tid < 8) atomicAdd(&d_planeSum[bc*8 + tid], bsum[tid]);
}

// ---------------- K2: g accumulation (the big one) ----------------
// grid (72, 8), block (16,16). 4 spatial tiles (8x16) per block.
__global__ void __launch_bounds__(256) k_g(const float* __restrict__ x) {
    __shared__ float Ssm[16*180];       // 16 planes, 10x18 halo
    __shared__ float Xsm[128*65];       // 128 pixels x 64 channels (padded)
    int b = blockIdx.y;
    int tx = threadIdx.x, ty = threadIdx.y;
    int tid = ty * 16 + tx;
    float acc[9][4];
#pragma unroll
    for (int j = 0; j < 9; j++)
#pragma unroll
        for (int m = 0; m < 4; m++) acc[j][m] = 0.f;

    for (int j = 0; j < 4; j++) {
        int t = blockIdx.x * 4 + j;
        int h0 = (t / 12) * 8, w0 = (t % 12) * 16;
        __syncthreads();
        for (int idx = tid; idx < 2880; idx += 256) {
            int sc = idx / 180, rem = idx % 180;
            int r = rem / 18, cc = rem % 18;
            int gh = h0 - 1 + r, gw = w0 - 1 + cc;
            float v = 0.f;
            if (gh >= 0 && gh < Hh && gw >= 0 && gw < Ww)
                v = d_space[(b*16 + sc)*HW + gh*Ww + gw];
            Ssm[idx] = v;
        }
        for (int idx = tid; idx < 8192; idx += 256) {
            int i = idx >> 7, p = idx & 127;
            Xsm[p*65 + i] = x[(b*64 + i)*HW + (h0 + (p >> 4))*Ww + (w0 + (p & 15))];
        }
        __syncthreads();
        const float* Sp = &Ssm[ty * 180];
        for (int k = 0; k < 128; k++) {
            int py = k >> 4, px = k & 15;
            int base = (py + 2) * 18 + (px + 2);
            float sv[9];
#pragma unroll
            for (int ky = 0; ky < 3; ky++)
#pragma unroll
                for (int kx = 0; kx < 3; kx++)
                    sv[ky*3 + kx] = Sp[base - ky*18 - kx];
            float xv[4];
#pragma unroll
            for (int m = 0; m < 4; m++)
                xv[m] = Xsm[k*65 + tx + 16*m];
#pragma unroll
            for (int jj = 0; jj < 9; jj++)
#pragma unroll
                for (int m = 0; m < 4; m++)
                    acc[jj][m] = fmaf(sv[jj], xv[m], acc[jj][m]);
        }
    }
#pragma unroll
    for (int jj = 0; jj < 9; jj++)
#pragma unroll
        for (int m = 0; m < 4; m++)
            atomicAdd(&d_g[((b*16 + ty)*9 + jj)*64 + tx + 16*m], acc[jj][m]);
}

// ---------------- K3a: tok2 ----------------
// grid 128 = (b, c, s), block 64 = d
__global__ void __launch_bounds__(64) k_tok2(const float* __restrict__ Wx,
                                             const float* __restrict__ Wcs) {
    __shared__ float gs[576];
    int id = blockIdx.x;
    int b = id >> 4, rem = id & 15, c = rem >> 3, s = rem & 7;
    int tid = threadIdx.x;
    for (int idx = tid; idx < 576; idx += 64)
        gs[idx] = d_g[(b*16 + c*8 + s)*576 + idx];
    __syncthreads();
    int d = tid;
    float a = 0.f;
    const float* wrow = Wx + (s*64 + d)*576;
    for (int i = 0; i < 64; i++) {
#pragma unroll
        for (int k = 0; k < 9; k++)
            a = fmaf(wrow[i*9 + k], gs[k*64 + i], a);
    }
    a *= Wcs[s] / d_planeSum[(b*2 + c)*8 + s];
    atomicAdd(&d_tok2[(b*2 + c)*64 + d], a);
}

// ---------------- K3b: Weff ----------------
// grid 16 = (b,c), block 576 = (o,k)
__global__ void __launch_bounds__(576) k_weff(const float* __restrict__ Ws) {
    __shared__ float t2[64];
    int bc = blockIdx.x;
    int tid = threadIdx.x;
    if (tid < 64) t2[tid] = d_tok2[bc*64 + tid];
    __syncthreads();
    int o = tid / 9, k = tid % 9;
    float a = 0.f;
#pragma unroll 8
    for (int d = 0; d < 64; d++)
        a = fmaf(t2[d], Ws[(o*64 + d)*9 + k], a);
    d_Weff[bc*576 + tid] = a;
}

// ---------------- K4: F map ----------------
__global__ void k_F(const float* __restrict__ Wcv, const float* __restrict__ Wat,
                    const float* __restrict__ Wcb) {
    int idx = blockIdx.x * blockDim.x + threadIdx.x;
    if (idx >= Bz*NC*HW) return;
    int bc = idx / HW, hw = idx % HW;
    float p = d_space[bc*8*HW + hw];   // s=0 plane == class_prob
    float f = 0.f;
#pragma unroll
    for (int s = 0; s < 8; s++)
        f = fmaf(Wcb[s] * Wcv[s], sigmf(p * Wat[s]), f);
    d_F[idx] = f;
}

// ---------------- K5: BN stats (sum, sumsq of y) ----------------
// grid (72, 8), block 256; tile 16 rows x 32 cols, 2 px/thread
__global__ void __launch_bounds__(256) k_stats() {
    __shared__ float Fh[2*18*34];
    __shared__ float Wsm[1152];
    int b = blockIdx.y;
    int t = blockIdx.x;
    int h0 = (t / 6) * 16, w0 = (t % 6) * 32;
    int tid = threadIdx.x;
    for (int idx = tid; idx < 1224; idx += 256) {
        int c = idx / 612, rem = idx % 612;
        int r = rem / 34, cc = rem % 34;
        int gh = h0 - 1 + r, gw = w0 - 1 + cc;
        float v = 0.f;
        if (gh >= 0 && gh < Hh && gw >= 0 && gw < Ww)
            v = d_F[(b*2 + c)*HW + gh*Ww + gw];
        Fh[idx] = v;
    }
    for (int idx = tid; idx < 1152; idx += 256)
        Wsm[idx] = d_Weff[b*1152 + idx];
    __syncthreads();
    int p0 = tid * 2;
    int py = p0 / 32, px = p0 % 32;
    float f0[18], f1[18];
#pragma unroll
    for (int c = 0; c < 2; c++)
#pragma unroll
        for (int ky = 0; ky < 3; ky++)
#pragma unroll
            for (int kx = 0; kx < 3; kx++) {
                f0[c*9 + ky*3 + kx] = Fh[c*612 + (py+ky)*34 + px + kx];
                f1[c*9 + ky*3 + kx] = Fh[c*612 + (py+ky)*34 + px + 1 + kx];
            }
    for (int o = 0; o < 64; o++) {
        float y0 = 0.f, y1 = 0.f;
#pragma unroll
        for (int c = 0; c < 2; c++)
#pragma unroll
            for (int kk = 0; kk < 9; kk++) {
                float w = Wsm[(c*64 + o)*9 + kk];
                y0 = fmaf(f0[c*9 + kk], w, y0);
                y1 = fmaf(f1[c*9 + kk], w, y1);
            }
        float s = y0 + y1;
        float q = y0*y0 + y1*y1;
#pragma unroll
        for (int off = 16; off > 0; off >>= 1) {
            s += __shfl_xor_sync(0xffffffffu, s, off);
            q += __shfl_xor_sync(0xffffffffu, q, off);
        }
        if ((tid & 31) == 0) {
            atomicAdd(&d_stat[o], (double)s);
            atomicAdd(&d_stat[64 + o], (double)q);
        }
    }
}

// ---------------- K6: finalize BN ----------------
__global__ void k_finalize(const float* __restrict__ gamma,
                           const float* __restrict__ beta) {
    int o = threadIdx.x;
    double N = (double)(Bz * HW);
    double mean = d_stat[o] / N;
    double var = d_stat[64 + o] / N - mean * mean;
    float al = gamma[o] * rsqrtf((float)var + 1e-5f);
    d_alpha[o] = al;
    d_beta2[o] = beta[o] - (float)mean * al;
}

// ---------------- K7: output = x + relu(BN(y)) ----------------
// grid (144, 8), block 256; tile 16x16
__global__ void __launch_bounds__(256) k_out(const float* __restrict__ x,
                                             float* __restrict__ out) {
    __shared__ float Fh[2*18*18];
    __shared__ float Wsm[1152];
    __shared__ float alsm[64], besm[64];
    int b = blockIdx.y;
    int t = blockIdx.x;
    int h0 = (t / 12) * 16, w0 = (t % 12) * 16;
    int tid = threadIdx.x;
    for (int idx = tid; idx < 648; idx += 256) {
        int c = idx / 324, rem = idx % 324;
        int r = rem / 18, cc = rem % 18;
        int gh = h0 - 1 + r, gw = w0 - 1 + cc;
        float v = 0.f;
        if (gh >= 0 && gh < Hh && gw >= 0 && gw < Ww)
            v = d_F[(b*2 + c)*HW + gh*Ww + gw];
        Fh[idx] = v;
    }
    for (int idx = tid; idx < 1152; idx += 256)
        Wsm[idx] = d_Weff[b*1152 + idx];
    if (tid < 64) { alsm[tid] = d_alpha[tid]; besm[tid] = d_beta2[tid]; }
    __syncthreads();
    int py = tid >> 4, px = tid & 15;
    float f[18];
#pragma unroll
    for (int c = 0; c < 2; c++)
#pragma unroll
        for (int ky = 0; ky < 3; ky++)
#pragma unroll
            for (int kx = 0; kx < 3; kx++)
                f[c*9 + ky*3 + kx] = Fh[c*324 + (py+ky)*18 + px + kx];
    int pix = (h0 + py) * Ww + (w0 + px);
    for (int o = 0; o < 64; o++) {
        float y = 0.f;
#pragma unroll
        for (int c = 0; c < 2; c++)
#pragma unroll
            for (int kk = 0; kk < 9; kk++)
                y = fmaf(f[c*9 + kk], Wsm[(c*64 + o)*9 + kk], y);
        float v = fmaf(alsm[o], y, besm[o]);
        v = v > 0.f ? v : 0.f;
        int off = (b*64 + o)*HW + pix;
        out[off] = x[off] + v;
    }
}

extern "C" void kernel_launch(void* const* d_in, const int* in_sizes, int n_in,
                              void* d_out, int out_size) {
    const float* x    = (const float*)d_in[0];
    const float* cls  = (const float*)d_in[1];
    const float* Wc   = (const float*)d_in[2];   // (7,1,3,3)
    const float* Wx   = (const float*)d_in[3];   // (512,64,3,3)
    const float* Wcs  = (const float*)d_in[4];   // (8,)
    const float* Wcv  = (const float*)d_in[5];   // (8,)
    const float* Wat  = (const float*)d_in[6];   // (8,)
    const float* Wcb  = (const float*)d_in[7];   // (8,)
    const float* Ws   = (const float*)d_in[8];   // (64,64,3,3)
    const float* gam  = (const float*)d_in[9];
    const float* bet  = (const float*)d_in[10];
    float* out = (float*)d_out;

    k_zero<<<288, 256>>>();
    k_space<<<dim3(12,12,16), 256>>>(cls, Wc);
    k_g<<<dim3(72,8), dim3(16,16)>>>(x);
    k_tok2<<<128, 64>>>(Wx, Wcs);
    k_weff<<<16, 576>>>(Ws);
    k_F<<<(Bz*NC*HW + 255)/256, 256>>>(Wcv, Wat, Wcb);
    k_stats<<<dim3(72,8), 256>>>();
    k_finalize<<<1, 64>>>(gam, bet);
    k_out<<<dim3(144,8), 256>>>(x, out);
}

// round 4
// speedup vs baseline: 1.6208x; 1.6208x over previous
#include <cuda_runtime.h>
#include <math.h>

#define Bz 8
#define NC 2
#define NS 8
#define Cc 64
#define Hh 192
#define Ww 192
#define HW (Hh*Ww)

typedef unsigned long long ull;

// ---- scratch (static __device__, no allocations) ----
__device__ float d_space[Bz*NC*NS*HW];   // sigmoid space planes [b][c*8+s][hw]
__device__ float d_planeSum[Bz*NC*NS];   // per-plane spatial sums
__device__ float d_g[Bz*16*576];         // [b][cs(16)][i*9+k]   (i-major now!)
__device__ float d_tok2[Bz*NC*Cc];       // [b][c][d]
__device__ float d_Weff[Bz*NC*Cc*9];     // [b][c][o][k]
__device__ float d_F[Bz*NC*HW];          // attention-combined scalar map
__device__ double d_stat[2*Cc];          // per-channel sum, sumsq of y
__device__ float d_alpha[Cc];
__device__ float d_beta2[Cc];

__device__ __forceinline__ float sigmf(float v) {
    return 1.0f / (1.0f + __expf(-v));
}

// ---- f32x2 packed helpers ----
__device__ __forceinline__ ull pack2(float v) {
    ull r; unsigned u = __float_as_uint(v);
    asm("mov.b64 %0, {%1, %1};" : "=l"(r) : "r"(u));
    return r;
}
__device__ __forceinline__ ull packab(float a, float b) {
    ull r; unsigned ua = __float_as_uint(a), ub = __float_as_uint(b);
    asm("mov.b64 %0, {%1, %2};" : "=l"(r) : "r"(ua), "r"(ub));
    return r;
}
__device__ __forceinline__ void fma2(ull &d, ull a, ull b) {
    asm("fma.rn.f32x2 %0, %1, %2, %0;" : "+l"(d) : "l"(a), "l"(b));
}
__device__ __forceinline__ float2 u2f(ull u) {
    float2 f; unsigned lo, hi;
    asm("mov.b64 {%0, %1}, %2;" : "=r"(lo), "=r"(hi) : "l"(u));
    f.x = __uint_as_float(lo); f.y = __uint_as_float(hi);
    return f;
}

// ---------------- K0: zero accumulators ----------------
__global__ void k_zero() {
    int i = blockIdx.x * blockDim.x + threadIdx.x;
    if (i < Bz*16*576) d_g[i] = 0.f;
    if (i < Bz*NC*NS) d_planeSum[i] = 0.f;
    if (i < Bz*NC*Cc) d_tok2[i] = 0.f;
    if (i < 2*Cc) d_stat[i] = 0.0;
}

// ---------------- K1: space planes + plane sums ----------------
// grid (12,12,16 planes), block 256
__global__ void __launch_bounds__(256) k_space(const float* __restrict__ cls,
                                               const float* __restrict__ Wc) {
    __shared__ float halo[18*18];
    __shared__ float wsm[63];
    __shared__ float bsum[8];
    int bc = blockIdx.z;
    int h0 = blockIdx.y * 16, w0 = blockIdx.x * 16;
    int tid = threadIdx.x;
    if (tid < 63) wsm[tid] = Wc[tid];
    if (tid < 8) bsum[tid] = 0.f;
    for (int idx = tid; idx < 324; idx += 256) {
        int r = idx / 18, cc = idx % 18;
        int gh = h0 - 1 + r, gw = w0 - 1 + cc;
        float v = 0.f;
        if (gh >= 0 && gh < Hh && gw >= 0 && gw < Ww)
            v = sigmf(cls[bc*HW + gh*Ww + gw]);
        halo[idx] = v;
    }
    __syncthreads();
    int py = tid >> 4, px = tid & 15;
    float vals[8];
    vals[0] = halo[(py+1)*18 + px + 1];
#pragma unroll
    for (int oc = 0; oc < 7; oc++) {
        float a = 0.f;
#pragma unroll
        for (int ky = 0; ky < 3; ky++)
#pragma unroll
            for (int kx = 0; kx < 3; kx++)
                a = fmaf(halo[(py+ky)*18 + px + kx], wsm[oc*9 + ky*3 + kx], a);
        vals[oc+1] = sigmf(a);
    }
    int pix = (h0 + py) * Ww + (w0 + px);
#pragma unroll
    for (int s = 0; s < 8; s++)
        d_space[(bc*8 + s)*HW + pix] = vals[s];
#pragma unroll
    for (int s = 0; s < 8; s++) {
        float r = vals[s];
#pragma unroll
        for (int off = 16; off > 0; off >>= 1)
            r += __shfl_xor_sync(0xffffffffu, r, off);
        if ((tid & 31) == 0) atomicAdd(&bsum[s], r);
    }
    __syncthreads();
    if (tid < 8) atomicAdd(&d_planeSum[bc*8 + tid], bsum[tid]);
}

// ---------------- K2: g accumulation (f32x2 packed, sliding window) ----------------
// grid (72, 8), block (8,16): tx = channel octet, ty = plane. 4 tiles (8x16 px) per block.
__global__ void __launch_bounds__(128, 4) k_g(const float* __restrict__ x) {
    __shared__ float Ssm[16*180];                  // 16 planes, 10x18 halo
    __shared__ __align__(16) float Xsm[128*72];    // 128 pixels x 64 ch (pad 72)
    int b = blockIdx.y;
    int tx = threadIdx.x;   // 0..7
    int ty = threadIdx.y;   // 0..15
    int tid = ty * 8 + tx;
    ull acc[9][4];
#pragma unroll
    for (int j = 0; j < 9; j++)
#pragma unroll
        for (int m = 0; m < 4; m++) acc[j][m] = 0ull;

    for (int jt = 0; jt < 4; ++jt) {
        int t = blockIdx.x * 4 + jt;
        int h0 = (t / 12) * 8, wb = (t % 12) * 16;
        __syncthreads();
        for (int idx = tid; idx < 2880; idx += 128) {
            int sc = idx / 180, rem = idx % 180;
            int r = rem / 18, cc = rem % 18;
            int gh = h0 - 1 + r, gw = wb - 1 + cc;
            float v = 0.f;
            if (gh >= 0 && gh < Hh && gw >= 0 && gw < Ww)
                v = d_space[(b*16 + sc)*HW + gh*Ww + gw];
            Ssm[idx] = v;
        }
        {
            int prow = tid >> 4, pcol = tid & 15;
            const float* xp = x + b*64*HW + (h0 + prow)*Ww + wb + pcol;
            float* xs = &Xsm[tid * 72];
#pragma unroll 4
            for (int i = 0; i < 64; i += 2) {
                float2 v;
                v.x = xp[i * HW];
                v.y = xp[(i + 1) * HW];
                *(float2*)&xs[i] = v;
            }
        }
        __syncthreads();
        const float* Sp = &Ssm[ty * 180];
        for (int py = 0; py < 8; ++py) {
            const float* R0 = Sp + (py + 2) * 18;  // ky=0
            const float* R1 = Sp + (py + 1) * 18;  // ky=1
            const float* R2 = Sp + (py + 0) * 18;  // ky=2
            ull w0a = pack2(R0[0]), w0b = pack2(R0[1]), w0c = pack2(R0[2]);
            ull w1a = pack2(R1[0]), w1b = pack2(R1[1]), w1c = pack2(R1[2]);
            ull w2a = pack2(R2[0]), w2b = pack2(R2[1]), w2c = pack2(R2[2]);
#pragma unroll
            for (int px = 0; px < 16; ++px) {
                int p = py * 16 + px;
                ulonglong2 xa = *(const ulonglong2*)&Xsm[p*72 + tx*8];
                ulonglong2 xb = *(const ulonglong2*)&Xsm[p*72 + tx*8 + 4];
                ull xv0 = xa.x, xv1 = xa.y, xv2 = xb.x, xv3 = xb.y;
                // sv[ky][kx] = col (px+2-kx): kx=0 -> *c, kx=1 -> *b, kx=2 -> *a
                fma2(acc[0][0], w0c, xv0); fma2(acc[0][1], w0c, xv1);
                fma2(acc[0][2], w0c, xv2); fma2(acc[0][3], w0c, xv3);
                fma2(acc[1][0], w0b, xv0); fma2(acc[1][1], w0b, xv1);
                fma2(acc[1][2], w0b, xv2); fma2(acc[1][3], w0b, xv3);
                fma2(acc[2][0], w0a, xv0); fma2(acc[2][1], w0a, xv1);
                fma2(acc[2][2], w0a, xv2); fma2(acc[2][3], w0a, xv3);
                fma2(acc[3][0], w1c, xv0); fma2(acc[3][1], w1c, xv1);
                fma2(acc[3][2], w1c, xv2); fma2(acc[3][3], w1c, xv3);
                fma2(acc[4][0], w1b, xv0); fma2(acc[4][1], w1b, xv1);
                fma2(acc[4][2], w1b, xv2); fma2(acc[4][3], w1b, xv3);
                fma2(acc[5][0], w1a, xv0); fma2(acc[5][1], w1a, xv1);
                fma2(acc[5][2], w1a, xv2); fma2(acc[5][3], w1a, xv3);
                fma2(acc[6][0], w2c, xv0); fma2(acc[6][1], w2c, xv1);
                fma2(acc[6][2], w2c, xv2); fma2(acc[6][3], w2c, xv3);
                fma2(acc[7][0], w2b, xv0); fma2(acc[7][1], w2b, xv1);
                fma2(acc[7][2], w2b, xv2); fma2(acc[7][3], w2b, xv3);
                fma2(acc[8][0], w2a, xv0); fma2(acc[8][1], w2a, xv1);
                fma2(acc[8][2], w2a, xv2); fma2(acc[8][3], w2a, xv3);
                w0a = w0b; w0b = w0c;
                w1a = w1b; w1b = w1c;
                w2a = w2b; w2b = w2c;
                if (px < 15) {
                    w0c = pack2(R0[px + 3]);
                    w1c = pack2(R1[px + 3]);
                    w2c = pack2(R2[px + 3]);
                }
            }
        }
    }
    float* gb = &d_g[(b*16 + ty) * 576];
#pragma unroll
    for (int j = 0; j < 9; j++)
#pragma unroll
        for (int m = 0; m < 4; m++) {
            float2 f = u2f(acc[j][m]);
            int i0 = tx*8 + 2*m;
            atomicAdd(&gb[i0*9 + j],     f.x);
            atomicAdd(&gb[(i0+1)*9 + j], f.y);
        }
}

// ---------------- K3a: tok2 ----------------
// grid (4 i-chunks, 8 s), block 256: d = tid&63, q = tid>>6 -> 4 bc each
__global__ void __launch_bounds__(256) k_tok2(const float* __restrict__ Wx,
                                              const float* __restrict__ Wcs) {
    __shared__ float gsm[16*144];
    __shared__ float scl[16];
    int s = blockIdx.y, ch = blockIdx.x;
    int tid = threadIdx.x;
    if (tid < 16) scl[tid] = Wcs[s] / d_planeSum[tid*8 + s];
    __syncthreads();
    for (int idx = tid; idx < 2304; idx += 256) {
        int bc = idx / 144, e = idx % 144;
        int plane = (bc >> 1)*16 + (bc & 1)*8 + s;
        gsm[idx] = d_g[plane*576 + ch*144 + e] * scl[bc];
    }
    __syncthreads();
    int d = tid & 63, q = tid >> 6;
    const float4* w4 = (const float4*)(Wx + (s*64 + d)*576 + ch*144);
    float a0 = 0.f, a1 = 0.f, a2 = 0.f, a3 = 0.f;
    const float4* g0 = (const float4*)&gsm[(q*4 + 0)*144];
    const float4* g1 = (const float4*)&gsm[(q*4 + 1)*144];
    const float4* g2 = (const float4*)&gsm[(q*4 + 2)*144];
    const float4* g3 = (const float4*)&gsm[(q*4 + 3)*144];
#pragma unroll 4
    for (int t = 0; t < 36; t++) {
        float4 w = w4[t];
        float4 v;
        v = g0[t]; a0 = fmaf(w.x,v.x,fmaf(w.y,v.y,fmaf(w.z,v.z,fmaf(w.w,v.w,a0))));
        v = g1[t]; a1 = fmaf(w.x,v.x,fmaf(w.y,v.y,fmaf(w.z,v.z,fmaf(w.w,v.w,a1))));
        v = g2[t]; a2 = fmaf(w.x,v.x,fmaf(w.y,v.y,fmaf(w.z,v.z,fmaf(w.w,v.w,a2))));
        v = g3[t]; a3 = fmaf(w.x,v.x,fmaf(w.y,v.y,fmaf(w.z,v.z,fmaf(w.w,v.w,a3))));
    }
    atomicAdd(&d_tok2[(q*4 + 0)*64 + d], a0);
    atomicAdd(&d_tok2[(q*4 + 1)*64 + d], a1);
    atomicAdd(&d_tok2[(q*4 + 2)*64 + d], a2);
    atomicAdd(&d_tok2[(q*4 + 3)*64 + d], a3);
}

// ---------------- K3b: Weff ----------------
__global__ void __launch_bounds__(576) k_weff(const float* __restrict__ Ws) {
    __shared__ float t2[64];
    int bc = blockIdx.x;
    int tid = threadIdx.x;
    if (tid < 64) t2[tid] = d_tok2[bc*64 + tid];
    __syncthreads();
    int o = tid / 9, k = tid % 9;
    float a = 0.f;
#pragma unroll 8
    for (int d = 0; d < 64; d++)
        a = fmaf(t2[d], Ws[(o*64 + d)*9 + k], a);
    d_Weff[bc*576 + tid] = a;
}

// ---------------- K4: F map ----------------
__global__ void k_F(const float* __restrict__ Wcv, const float* __restrict__ Wat,
                    const float* __restrict__ Wcb) {
    int idx = blockIdx.x * blockDim.x + threadIdx.x;
    if (idx >= Bz*NC*HW) return;
    int bc = idx / HW, hw = idx % HW;
    float p = d_space[bc*8*HW + hw];   // s=0 plane == class_prob
    float f = 0.f;
#pragma unroll
    for (int s = 0; s < 8; s++)
        f = fmaf(Wcb[s] * Wcv[s], sigmf(p * Wat[s]), f);
    d_F[idx] = f;
}

// ---------------- K5: BN stats (sum, sumsq of y), 8 px/thread, f32x2 ----------------
// grid (36, 8), block 128; tile 16 rows x 64 cols
__global__ void __launch_bounds__(128) k_stats() {
    __shared__ float Fh[2*18*68];
    __shared__ ull wp[1152];
    int b = blockIdx.y, t = blockIdx.x;
    int h0 = (t / 3) * 16, w0 = (t % 3) * 64;
    int tid = threadIdx.x;
    for (int idx = tid; idx < 2*18*66; idx += 128) {
        int c = idx / (18*66), rem = idx % (18*66);
        int r = rem / 66, cc = rem % 66;
        int gh = h0 - 1 + r, gw = w0 - 1 + cc;
        float v = 0.f;
        if (gh >= 0 && gh < Hh && gw >= 0 && gw < Ww)
            v = d_F[(b*2 + c)*HW + gh*Ww + gw];
        Fh[c*1224 + r*68 + cc] = v;
    }
    for (int idx = tid; idx < 1152; idx += 128)
        wp[idx] = pack2(d_Weff[b*1152 + idx]);
    __syncthreads();
    int rowp = tid >> 3, tx = tid & 7, px0 = tx * 8;
    ull p2[2][3][9];
#pragma unroll
    for (int c = 0; c < 2; c++)
#pragma unroll
        for (int ky = 0; ky < 3; ky++) {
            const float* Fr = &Fh[c*1224 + (rowp + ky)*68 + px0];
            float prev = Fr[0];
#pragma unroll
            for (int tt = 0; tt < 9; tt++) {
                float cur = Fr[tt + 1];
                p2[c][ky][tt] = packab(prev, cur);
                prev = cur;
            }
        }
    for (int o = 0; o < 64; o++) {
        ull y0 = 0, y1 = 0, y2 = 0, y3 = 0;
#pragma unroll
        for (int c = 0; c < 2; c++)
#pragma unroll
            for (int kk = 0; kk < 9; kk++) {
                ull w = wp[(c*64 + o)*9 + kk];
                int ky = kk / 3, kx = kk % 3;
                fma2(y0, p2[c][ky][kx],     w);
                fma2(y1, p2[c][ky][2 + kx], w);
                fma2(y2, p2[c][ky][4 + kx], w);
                fma2(y3, p2[c][ky][6 + kx], w);
            }
        float2 f0 = u2f(y0), f1 = u2f(y1), f2 = u2f(y2), f3 = u2f(y3);
        float s = f0.x + f0.y + f1.x + f1.y + f2.x + f2.y + f3.x + f3.y;
        float q = f0.x*f0.x + f0.y*f0.y + f1.x*f1.x + f1.y*f1.y
                + f2.x*f2.x + f2.y*f2.y + f3.x*f3.x + f3.y*f3.y;
#pragma unroll
        for (int off = 16; off > 0; off >>= 1) {
            s += __shfl_xor_sync(0xffffffffu, s, off);
            q += __shfl_xor_sync(0xffffffffu, q, off);
        }
        if ((tid & 31) == 0) {
            atomicAdd(&d_stat[o], (double)s);
            atomicAdd(&d_stat[64 + o], (double)q);
        }
    }
}

// ---------------- K6: finalize BN ----------------
__global__ void k_finalize(const float* __restrict__ gamma,
                           const float* __restrict__ beta) {
    int o = threadIdx.x;
    double N = (double)(Bz * HW);
    double mean = d_stat[o] / N;
    double var = d_stat[64 + o] / N - mean * mean;
    float al = gamma[o] * rsqrtf((float)var + 1e-5f);
    d_alpha[o] = al;
    d_beta2[o] = beta[o] - (float)mean * al;
}

// ---------------- K7: output = x + relu(BN(y)), 8 px/thread, f32x2 ----------------
// grid (36, 8), block 128; tile 16 rows x 64 cols
__global__ void __launch_bounds__(128) k_out(const float* __restrict__ x,
                                             float* __restrict__ out) {
    __shared__ float Fh[2*18*68];
    __shared__ ull wp[1152];
    __shared__ float alsm[64], besm[64];
    int b = blockIdx.y, t = blockIdx.x;
    int h0 = (t / 3) * 16, w0 = (t % 3) * 64;
    int tid = threadIdx.x;
    for (int idx = tid; idx < 2*18*66; idx += 128) {
        int c = idx / (18*66), rem = idx % (18*66);
        int r = rem / 66, cc = rem % 66;
        int gh = h0 - 1 + r, gw = w0 - 1 + cc;
        float v = 0.f;
        if (gh >= 0 && gh < Hh && gw >= 0 && gw < Ww)
            v = d_F[(b*2 + c)*HW + gh*Ww + gw];
        Fh[c*1224 + r*68 + cc] = v;
    }
    for (int idx = tid; idx < 1152; idx += 128)
        wp[idx] = pack2(d_Weff[b*1152 + idx]);
    if (tid < 64) { alsm[tid] = d_alpha[tid]; besm[tid] = d_beta2[tid]; }
    __syncthreads();
    int rowp = tid >> 3, tx = tid & 7, px0 = tx * 8;
    ull p2[2][3][9];
#pragma unroll
    for (int c = 0; c < 2; c++)
#pragma unroll
        for (int ky = 0; ky < 3; ky++) {
            const float* Fr = &Fh[c*1224 + (rowp + ky)*68 + px0];
            float prev = Fr[0];
#pragma unroll
            for (int tt = 0; tt < 9; tt++) {
                float cur = Fr[tt + 1];
                p2[c][ky][tt] = packab(prev, cur);
                prev = cur;
            }
        }
    int pixbase = (h0 + rowp) * Ww + w0 + px0;
    for (int o = 0; o < 64; o++) {
        ull y0 = 0, y1 = 0, y2 = 0, y3 = 0;
#pragma unroll
        for (int c = 0; c < 2; c++)
#pragma unroll
            for (int kk = 0; kk < 9; kk++) {
                ull w = wp[(c*64 + o)*9 + kk];
                int ky = kk / 3, kx = kk % 3;
                fma2(y0, p2[c][ky][kx],     w);
                fma2(y1, p2[c][ky][2 + kx], w);
                fma2(y2, p2[c][ky][4 + kx], w);
                fma2(y3, p2[c][ky][6 + kx], w);
            }
        float al = alsm[o], be = besm[o];
        float2 f0 = u2f(y0), f1 = u2f(y1), f2 = u2f(y2), f3 = u2f(y3);
        long off = (long)(b*64 + o)*HW + pixbase;
        const float4* xq = (const float4*)(x + off);
        float4 xa = xq[0], xb = xq[1];
        float4 ra, rb;
        ra.x = xa.x + fmaxf(fmaf(al, f0.x, be), 0.f);
        ra.y = xa.y + fmaxf(fmaf(al, f0.y, be), 0.f);
        ra.z = xa.z + fmaxf(fmaf(al, f1.x, be), 0.f);
        ra.w = xa.w + fmaxf(fmaf(al, f1.y, be), 0.f);
        rb.x = xb.x + fmaxf(fmaf(al, f2.x, be), 0.f);
        rb.y = xb.y + fmaxf(fmaf(al, f2.y, be), 0.f);
        rb.z = xb.z + fmaxf(fmaf(al, f3.x, be), 0.f);
        rb.w = xb.w + fmaxf(fmaf(al, f3.y, be), 0.f);
        float4* oq = (float4*)(out + off);
        oq[0] = ra;
        oq[1] = rb;
    }
}

extern "C" void kernel_launch(void* const* d_in, const int* in_sizes, int n_in,
                              void* d_out, int out_size) {
    const float* x    = (const float*)d_in[0];
    const float* cls  = (const float*)d_in[1];
    const float* Wc   = (const float*)d_in[2];
    const float* Wx   = (const float*)d_in[3];
    const float* Wcs  = (const float*)d_in[4];
    const float* Wcv  = (const float*)d_in[5];
    const float* Wat  = (const float*)d_in[6];
    const float* Wcb  = (const float*)d_in[7];
    const float* Ws   = (const float*)d_in[8];
    const float* gam  = (const float*)d_in[9];
    const float* bet  = (const float*)d_in[10];
    float* out = (float*)d_out;

    k_zero<<<288, 256>>>();
    k_space<<<dim3(12,12,16), 256>>>(cls, Wc);
    k_g<<<dim3(72,8), dim3(8,16)>>>(x);
    k_tok2<<<dim3(4,8), 256>>>(Wx, Wcs);
    k_weff<<<16, 576>>>(Ws);
    k_F<<<(Bz*NC*HW + 255)/256, 256>>>(Wcv, Wat, Wcb);
    k_stats<<<dim3(36,8), 128>>>();
    k_finalize<<<1, 64>>>(gam, bet);
    k_out<<<dim3(36,8), 128>>>(x, out);
}

// round 5
// speedup vs baseline: 1.6669x; 1.0284x over previous
#include <cuda_runtime.h>
#include <math.h>

#define Bz 8
#define NC 2
#define NS 8
#define Cc 64
#define Hh 192
#define Ww 192
#define HW (Hh*Ww)

typedef unsigned long long ull;

// ---- scratch (static __device__, no allocations) ----
__device__ float d_space[Bz*NC*NS*HW];   // sigmoid space planes [b][c*8+s][hw]
__device__ float d_planeSum[Bz*NC*NS];   // per-plane spatial sums
__device__ float d_g[Bz*16*576];         // [b][cs(16)][i*9+k]   (i-major)
__device__ float d_tok2[Bz*NC*Cc];       // [b][c][d]
__device__ float d_Weff[Bz*NC*Cc*9];     // [b][c][o][k]
__device__ float d_F[Bz*NC*HW];          // attention-combined scalar map
__device__ double d_stat[2*Cc];          // per-channel sum, sumsq of y
__device__ float d_alpha[Cc];
__device__ float d_beta2[Cc];

__device__ __forceinline__ float sigmf(float v) {
    return 1.0f / (1.0f + __expf(-v));
}

// ---- f32x2 packed helpers ----
__device__ __forceinline__ ull pack2(float v) {
    ull r; unsigned u = __float_as_uint(v);
    asm("mov.b64 %0, {%1, %1};" : "=l"(r) : "r"(u));
    return r;
}
__device__ __forceinline__ ull packab(float a, float b) {
    ull r; unsigned ua = __float_as_uint(a), ub = __float_as_uint(b);
    asm("mov.b64 %0, {%1, %2};" : "=l"(r) : "r"(ua), "r"(ub));
    return r;
}
__device__ __forceinline__ void fma2(ull &d, ull a, ull b) {
    asm("fma.rn.f32x2 %0, %1, %2, %0;" : "+l"(d) : "l"(a), "l"(b));
}
__device__ __forceinline__ float2 u2f(ull u) {
    float2 f; unsigned lo, hi;
    asm("mov.b64 {%0, %1}, %2;" : "=r"(lo), "=r"(hi) : "l"(u));
    f.x = __uint_as_float(lo); f.y = __uint_as_float(hi);
    return f;
}

// ---------------- K0: zero accumulators ----------------
__global__ void k_zero() {
    int i = blockIdx.x * blockDim.x + threadIdx.x;
    if (i < Bz*16*576) d_g[i] = 0.f;
    if (i < Bz*NC*NS) d_planeSum[i] = 0.f;
    if (i < Bz*NC*Cc) d_tok2[i] = 0.f;
    if (i < 2*Cc) d_stat[i] = 0.0;
}

// ---------------- K1: space planes + plane sums ----------------
// grid (12,12,16 planes), block 256
__global__ void __launch_bounds__(256) k_space(const float* __restrict__ cls,
                                               const float* __restrict__ Wc) {
    __shared__ float halo[18*18];
    __shared__ float wsm[63];
    __shared__ float bsum[8];
    int bc = blockIdx.z;
    int h0 = blockIdx.y * 16, w0 = blockIdx.x * 16;
    int tid = threadIdx.x;
    if (tid < 63) wsm[tid] = Wc[tid];
    if (tid < 8) bsum[tid] = 0.f;
    for (int idx = tid; idx < 324; idx += 256) {
        int r = idx / 18, cc = idx % 18;
        int gh = h0 - 1 + r, gw = w0 - 1 + cc;
        float v = 0.f;
        if (gh >= 0 && gh < Hh && gw >= 0 && gw < Ww)
            v = sigmf(cls[bc*HW + gh*Ww + gw]);
        halo[idx] = v;
    }
    __syncthreads();
    int py = tid >> 4, px = tid & 15;
    float vals[8];
    vals[0] = halo[(py+1)*18 + px + 1];
#pragma unroll
    for (int oc = 0; oc < 7; oc++) {
        float a = 0.f;
#pragma unroll
        for (int ky = 0; ky < 3; ky++)
#pragma unroll
            for (int kx = 0; kx < 3; kx++)
                a = fmaf(halo[(py+ky)*18 + px + kx], wsm[oc*9 + ky*3 + kx], a);
        vals[oc+1] = sigmf(a);
    }
    int pix = (h0 + py) * Ww + (w0 + px);
#pragma unroll
    for (int s = 0; s < 8; s++)
        d_space[(bc*8 + s)*HW + pix] = vals[s];
#pragma unroll
    for (int s = 0; s < 8; s++) {
        float r = vals[s];
#pragma unroll
        for (int off = 16; off > 0; off >>= 1)
            r += __shfl_xor_sync(0xffffffffu, r, off);
        if ((tid & 31) == 0) atomicAdd(&bsum[s], r);
    }
    __syncthreads();
    if (tid < 8) atomicAdd(&d_planeSum[bc*8 + tid], bsum[tid]);
}

// ---------------- K2: g accumulation (f32x2 packed, sliding window) ----------------
// grid (72, 8), block (8,16): tx = channel octet, ty = plane. 4 tiles (8x16 px) per block.
// launch_bounds (128,3): 170-reg budget so the 36 ull accumulators never spill.
__global__ void __launch_bounds__(128, 3) k_g(const float* __restrict__ x) {
    __shared__ float Ssm[16*180];                  // 16 planes, 10x18 halo
    __shared__ __align__(16) float Xsm[128*72];    // 128 pixels x 64 ch (pad 72)
    int b = blockIdx.y;
    int tx = threadIdx.x;   // 0..7
    int ty = threadIdx.y;   // 0..15
    int tid = ty * 8 + tx;
    ull acc[9][4];
#pragma unroll
    for (int j = 0; j < 9; j++)
#pragma unroll
        for (int m = 0; m < 4; m++) acc[j][m] = 0ull;

    for (int jt = 0; jt < 4; ++jt) {
        int t = blockIdx.x * 4 + jt;
        int h0 = (t / 12) * 8, wb = (t % 12) * 16;
        __syncthreads();
        for (int idx = tid; idx < 2880; idx += 128) {
            int sc = idx / 180, rem = idx % 180;
            int r = rem / 18, cc = rem % 18;
            int gh = h0 - 1 + r, gw = wb - 1 + cc;
            float v = 0.f;
            if (gh >= 0 && gh < Hh && gw >= 0 && gw < Ww)
                v = d_space[(b*16 + sc)*HW + gh*Ww + gw];
            Ssm[idx] = v;
        }
        {
            int prow = tid >> 4, pcol = tid & 15;
            const float* xp = x + b*64*HW + (h0 + prow)*Ww + wb + pcol;
            float* xs = &Xsm[tid * 72];
#pragma unroll 4
            for (int i = 0; i < 64; i += 2) {
                float2 v;
                v.x = xp[i * HW];
                v.y = xp[(i + 1) * HW];
                *(float2*)&xs[i] = v;
            }
        }
        __syncthreads();
        const float* Sp = &Ssm[ty * 180];
        for (int py = 0; py < 8; ++py) {
            const float* R0 = Sp + (py + 2) * 18;  // ky=0
            const float* R1 = Sp + (py + 1) * 18;  // ky=1
            const float* R2 = Sp + (py + 0) * 18;  // ky=2
            ull w0a = pack2(R0[0]), w0b = pack2(R0[1]), w0c = pack2(R0[2]);
            ull w1a = pack2(R1[0]), w1b = pack2(R1[1]), w1c = pack2(R1[2]);
            ull w2a = pack2(R2[0]), w2b = pack2(R2[1]), w2c = pack2(R2[2]);
#pragma unroll
            for (int px = 0; px < 16; ++px) {
                int p = py * 16 + px;
                ulonglong2 xa = *(const ulonglong2*)&Xsm[p*72 + tx*8];
                ulonglong2 xb = *(const ulonglong2*)&Xsm[p*72 + tx*8 + 4];
                ull xv0 = xa.x, xv1 = xa.y, xv2 = xb.x, xv3 = xb.y;
                fma2(acc[0][0], w0c, xv0); fma2(acc[0][1], w0c, xv1);
                fma2(acc[0][2], w0c, xv2); fma2(acc[0][3], w0c, xv3);
                fma2(acc[1][0], w0b, xv0); fma2(acc[1][1], w0b, xv1);
                fma2(acc[1][2], w0b, xv2); fma2(acc[1][3], w0b, xv3);
                fma2(acc[2][0], w0a, xv0); fma2(acc[2][1], w0a, xv1);
                fma2(acc[2][2], w0a, xv2); fma2(acc[2][3], w0a, xv3);
                fma2(acc[3][0], w1c, xv0); fma2(acc[3][1], w1c, xv1);
                fma2(acc[3][2], w1c, xv2); fma2(acc[3][3], w1c, xv3);
                fma2(acc[4][0], w1b, xv0); fma2(acc[4][1], w1b, xv1);
                fma2(acc[4][2], w1b, xv2); fma2(acc[4][3], w1b, xv3);
                fma2(acc[5][0], w1a, xv0); fma2(acc[5][1], w1a, xv1);
                fma2(acc[5][2], w1a, xv2); fma2(acc[5][3], w1a, xv3);
                fma2(acc[6][0], w2c, xv0); fma2(acc[6][1], w2c, xv1);
                fma2(acc[6][2], w2c, xv2); fma2(acc[6][3], w2c, xv3);
                fma2(acc[7][0], w2b, xv0); fma2(acc[7][1], w2b, xv1);
                fma2(acc[7][2], w2b, xv2); fma2(acc[7][3], w2b, xv3);
                fma2(acc[8][0], w2a, xv0); fma2(acc[8][1], w2a, xv1);
                fma2(acc[8][2], w2a, xv2); fma2(acc[8][3], w2a, xv3);
                w0a = w0b; w0b = w0c;
                w1a = w1b; w1b = w1c;
                w2a = w2b; w2b = w2c;
                if (px < 15) {
                    w0c = pack2(R0[px + 3]);
                    w1c = pack2(R1[px + 3]);
                    w2c = pack2(R2[px + 3]);
                }
            }
        }
    }
    float* gb = &d_g[(b*16 + ty) * 576];
#pragma unroll
    for (int j = 0; j < 9; j++)
#pragma unroll
        for (int m = 0; m < 4; m++) {
            float2 f = u2f(acc[j][m]);
            int i0 = tx*8 + 2*m;
            atomicAdd(&gb[i0*9 + j],     f.x);
            atomicAdd(&gb[(i0+1)*9 + j], f.y);
        }
}

// ---------------- K3a: tok2 ----------------
// grid (16 chunk, 8 s), block 256: each block handles a 36-float slice of the
// 576-long reduction for all 16 (b,c) and all 64 d. 128 blocks -> full-chip MLP.
__global__ void __launch_bounds__(256) k_tok2(const float* __restrict__ Wx,
                                              const float* __restrict__ Wcs) {
    __shared__ float gsm[16*36];
    __shared__ float scl[16];
    int s = blockIdx.y, ck = blockIdx.x;   // ck: 36-float chunk of 576
    int tid = threadIdx.x;
    if (tid < 16) scl[tid] = Wcs[s] / d_planeSum[tid*8 + s];
    __syncthreads();
    for (int idx = tid; idx < 576; idx += 256) {
        int bc = idx / 36, e = idx % 36;
        int plane = (bc >> 1)*16 + (bc & 1)*8 + s;
        gsm[idx] = d_g[plane*576 + ck*36 + e] * scl[bc];
    }
    __syncthreads();
    int d = tid & 63, q = tid >> 6;
    const float4* w4 = (const float4*)(Wx + (s*64 + d)*576 + ck*36);
    float a0 = 0.f, a1 = 0.f, a2 = 0.f, a3 = 0.f;
    const float4* g0 = (const float4*)&gsm[(q*4 + 0)*36];
    const float4* g1 = (const float4*)&gsm[(q*4 + 1)*36];
    const float4* g2 = (const float4*)&gsm[(q*4 + 2)*36];
    const float4* g3 = (const float4*)&gsm[(q*4 + 3)*36];
#pragma unroll
    for (int t = 0; t < 9; t++) {
        float4 w = w4[t];
        float4 v;
        v = g0[t]; a0 = fmaf(w.x,v.x,fmaf(w.y,v.y,fmaf(w.z,v.z,fmaf(w.w,v.w,a0))));
        v = g1[t]; a1 = fmaf(w.x,v.x,fmaf(w.y,v.y,fmaf(w.z,v.z,fmaf(w.w,v.w,a1))));
        v = g2[t]; a2 = fmaf(w.x,v.x,fmaf(w.y,v.y,fmaf(w.z,v.z,fmaf(w.w,v.w,a2))));
        v = g3[t]; a3 = fmaf(w.x,v.x,fmaf(w.y,v.y,fmaf(w.z,v.z,fmaf(w.w,v.w,a3))));
    }
    atomicAdd(&d_tok2[(q*4 + 0)*64 + d], a0);
    atomicAdd(&d_tok2[(q*4 + 1)*64 + d], a1);
    atomicAdd(&d_tok2[(q*4 + 2)*64 + d], a2);
    atomicAdd(&d_tok2[(q*4 + 3)*64 + d], a3);
}

// ---------------- K3b: Weff ----------------
__global__ void __launch_bounds__(576) k_weff(const float* __restrict__ Ws) {
    __shared__ float t2[64];
    int bc = blockIdx.x;
    int tid = threadIdx.x;
    if (tid < 64) t2[tid] = d_tok2[bc*64 + tid];
    __syncthreads();
    int o = tid / 9, k = tid % 9;
    float a = 0.f;
#pragma unroll 8
    for (int d = 0; d < 64; d++)
        a = fmaf(t2[d], Ws[(o*64 + d)*9 + k], a);
    d_Weff[bc*576 + tid] = a;
}

// ---------------- K4: F map ----------------
__global__ void k_F(const float* __restrict__ Wcv, const float* __restrict__ Wat,
                    const float* __restrict__ Wcb) {
    int idx = blockIdx.x * blockDim.x + threadIdx.x;
    if (idx >= Bz*NC*HW) return;
    int bc = idx / HW, hw = idx % HW;
    float p = d_space[bc*8*HW + hw];   // s=0 plane == class_prob
    float f = 0.f;
#pragma unroll
    for (int s = 0; s < 8; s++)
        f = fmaf(Wcb[s] * Wcv[s], sigmf(p * Wat[s]), f);
    d_F[idx] = f;
}

// ---------------- K5: BN stats (sum, sumsq of y), 8 px/thread, f32x2 ----------------
// grid (36, 8), block 128; tile 16 rows x 64 cols
__global__ void __launch_bounds__(128) k_stats() {
    __shared__ float Fh[2*18*68];
    __shared__ ull wp[1152];
    int b = blockIdx.y, t = blockIdx.x;
    int h0 = (t / 3) * 16, w0 = (t % 3) * 64;
    int tid = threadIdx.x;
    for (int idx = tid; idx < 2*18*66; idx += 128) {
        int c = idx / (18*66), rem = idx % (18*66);
        int r = rem / 66, cc = rem % 66;
        int gh = h0 - 1 + r, gw = w0 - 1 + cc;
        float v = 0.f;
        if (gh >= 0 && gh < Hh && gw >= 0 && gw < Ww)
            v = d_F[(b*2 + c)*HW + gh*Ww + gw];
        Fh[c*1224 + r*68 + cc] = v;
    }
    for (int idx = tid; idx < 1152; idx += 128)
        wp[idx] = pack2(d_Weff[b*1152 + idx]);
    __syncthreads();
    int rowp = tid >> 3, tx = tid & 7, px0 = tx * 8;
    ull p2[2][3][9];
#pragma unroll
    for (int c = 0; c < 2; c++)
#pragma unroll
        for (int ky = 0; ky < 3; ky++) {
            const float* Fr = &Fh[c*1224 + (rowp + ky)*68 + px0];
            float prev = Fr[0];
#pragma unroll
            for (int tt = 0; tt < 9; tt++) {
                float cur = Fr[tt + 1];
                p2[c][ky][tt] = packab(prev, cur);
                prev = cur;
            }
        }
    for (int o = 0; o < 64; o++) {
        ull y0 = 0, y1 = 0, y2 = 0, y3 = 0;
#pragma unroll
        for (int c = 0; c < 2; c++)
#pragma unroll
            for (int kk = 0; kk < 9; kk++) {
                ull w = wp[(c*64 + o)*9 + kk];
                int ky = kk / 3, kx = kk % 3;
                fma2(y0, p2[c][ky][kx],     w);
                fma2(y1, p2[c][ky][2 + kx], w);
                fma2(y2, p2[c][ky][4 + kx], w);
                fma2(y3, p2[c][ky][6 + kx], w);
            }
        float2 f0 = u2f(y0), f1 = u2f(y1), f2 = u2f(y2), f3 = u2f(y3);
        float s = f0.x + f0.y + f1.x + f1.y + f2.x + f2.y + f3.x + f3.y;
        float q = f0.x*f0.x + f0.y*f0.y + f1.x*f1.x + f1.y*f1.y
                + f2.x*f2.x + f2.y*f2.y + f3.x*f3.x + f3.y*f3.y;
#pragma unroll
        for (int off = 16; off > 0; off >>= 1) {
            s += __shfl_xor_sync(0xffffffffu, s, off);
            q += __shfl_xor_sync(0xffffffffu, q, off);
        }
        if ((tid & 31) == 0) {
            atomicAdd(&d_stat[o], (double)s);
            atomicAdd(&d_stat[64 + o], (double)q);
        }
    }
}

// ---------------- K6: finalize BN ----------------
__global__ void k_finalize(const float* __restrict__ gamma,
                           const float* __restrict__ beta) {
    int o = threadIdx.x;
    double N = (double)(Bz * HW);
    double mean = d_stat[o] / N;
    double var = d_stat[64 + o] / N - mean * mean;
    float al = gamma[o] * rsqrtf((float)var + 1e-5f);
    d_alpha[o] = al;
    d_beta2[o] = beta[o] - (float)mean * al;
}

// ---------------- K7: output = x + relu(BN(y)), 8 px/thread, f32x2 ----------------
// grid (36, 8), block 128; tile 16 rows x 64 cols
__global__ void __launch_bounds__(128) k_out(const float* __restrict__ x,
                                             float* __restrict__ out) {
    __shared__ float Fh[2*18*68];
    __shared__ ull wp[1152];
    __shared__ float alsm[64], besm[64];
    int b = blockIdx.y, t = blockIdx.x;
    int h0 = (t / 3) * 16, w0 = (t % 3) * 64;
    int tid = threadIdx.x;
    for (int idx = tid; idx < 2*18*66; idx += 128) {
        int c = idx / (18*66), rem = idx % (18*66);
        int r = rem / 66, cc = rem % 66;
        int gh = h0 - 1 + r, gw = w0 - 1 + cc;
        float v = 0.f;
        if (gh >= 0 && gh < Hh && gw >= 0 && gw < Ww)
            v = d_F[(b*2 + c)*HW + gh*Ww + gw];
        Fh[c*1224 + r*68 + cc] = v;
    }
    for (int idx = tid; idx < 1152; idx += 128)
        wp[idx] = pack2(d_Weff[b*1152 + idx]);
    if (tid < 64) { alsm[tid] = d_alpha[tid]; besm[tid] = d_beta2[tid]; }
    __syncthreads();
    int rowp = tid >> 3, tx = tid & 7, px0 = tx * 8;
    ull p2[2][3][9];
#pragma unroll
    for (int c = 0; c < 2; c++)
#pragma unroll
        for (int ky = 0; ky < 3; ky++) {
            const float* Fr = &Fh[c*1224 + (rowp + ky)*68 + px0];
            float prev = Fr[0];
#pragma unroll
            for (int tt = 0; tt < 9; tt++) {
                float cur = Fr[tt + 1];
                p2[c][ky][tt] = packab(prev, cur);
                prev = cur;
            }
        }
    int pixbase = (h0 + rowp) * Ww + w0 + px0;
    for (int o = 0; o < 64; o++) {
        ull y0 = 0, y1 = 0, y2 = 0, y3 = 0;
#pragma unroll
        for (int c = 0; c < 2; c++)
#pragma unroll
            for (int kk = 0; kk < 9; kk++) {
                ull w = wp[(c*64 + o)*9 + kk];
                int ky = kk / 3, kx = kk % 3;
                fma2(y0, p2[c][ky][kx],     w);
                fma2(y1, p2[c][ky][2 + kx], w);
                fma2(y2, p2[c][ky][4 + kx], w);
                fma2(y3, p2[c][ky][6 + kx], w);
            }
        float al = alsm[o], be = besm[o];
        float2 f0 = u2f(y0), f1 = u2f(y1), f2 = u2f(y2), f3 = u2f(y3);
        long off = (long)(b*64 + o)*HW + pixbase;
        const float4* xq = (const float4*)(x + off);
        float4 xa = xq[0], xb = xq[1];
        float4 ra, rb;
        ra.x = xa.x + fmaxf(fmaf(al, f0.x, be), 0.f);
        ra.y = xa.y + fmaxf(fmaf(al, f0.y, be), 0.f);
        ra.z = xa.z + fmaxf(fmaf(al, f1.x, be), 0.f);
        ra.w = xa.w + fmaxf(fmaf(al, f1.y, be), 0.f);
        rb.x = xb.x + fmaxf(fmaf(al, f2.x, be), 0.f);
        rb.y = xb.y + fmaxf(fmaf(al, f2.y, be), 0.f);
        rb.z = xb.z + fmaxf(fmaf(al, f3.x, be), 0.f);
        rb.w = xb.w + fmaxf(fmaf(al, f3.y, be), 0.f);
        float4* oq = (float4*)(out + off);
        oq[0] = ra;
        oq[1] = rb;
    }
}

extern "C" void kernel_launch(void* const* d_in, const int* in_sizes, int n_in,
                              void* d_out, int out_size) {
    const float* x    = (const float*)d_in[0];
    const float* cls  = (const float*)d_in[1];
    const float* Wc   = (const float*)d_in[2];
    const float* Wx   = (const float*)d_in[3];
    const float* Wcs  = (const float*)d_in[4];
    const float* Wcv  = (const float*)d_in[5];
    const float* Wat  = (const float*)d_in[6];
    const float* Wcb  = (const float*)d_in[7];
    const float* Ws   = (const float*)d_in[8];
    const float* gam  = (const float*)d_in[9];
    const float* bet  = (const float*)d_in[10];
    float* out = (float*)d_out;

    k_zero<<<288, 256>>>();
    k_space<<<dim3(12,12,16), 256>>>(cls, Wc);
    k_g<<<dim3(72,8), dim3(8,16)>>>(x);
    k_tok2<<<dim3(16,8), 256>>>(Wx, Wcs);
    k_weff<<<16, 576>>>(Ws);
    k_F<<<(Bz*NC*HW + 255)/256, 256>>>(Wcv, Wat, Wcb);
    k_stats<<<dim3(36,8), 128>>>();
    k_finalize<<<1, 64>>>(gam, bet);
    k_out<<<dim3(36,8), 128>>>(x, out);
}

// round 7
// speedup vs baseline: 1.7709x; 1.0624x over previous
#include <cuda_runtime.h>
#include <math.h>

#define Bz 8
#define NC 2
#define NS 8
#define Cc 64
#define Hh 192
#define Ww 192
#define HW (Hh*Ww)

typedef unsigned long long ull;

// ---- scratch (static __device__, no allocations) ----
__device__ float d_space[Bz*NC*NS*HW];   // sigmoid space planes [b][c*8+s][hw]
__device__ float d_planeSum[Bz*NC*NS];   // per-plane spatial sums
__device__ float d_g[Bz*16*576];         // [b][cs(16)][i*9+k]   (i-major)
__device__ float d_tok2[Bz*NC*Cc];       // [b][c][d]
__device__ float d_Weff[Bz*NC*Cc*9];     // [b][c][o][k]
__device__ float d_F[Bz*NC*HW];          // attention-combined scalar map
__device__ double d_stat[2*Cc];          // per-channel sum, sumsq of y
__device__ float d_alpha[Cc];
__device__ float d_beta2[Cc];

__device__ __forceinline__ float sigmf(float v) {
    return 1.0f / (1.0f + __expf(-v));
}

// ---- f32x2 packed helpers ----
__device__ __forceinline__ ull pack2(float v) {
    ull r; unsigned u = __float_as_uint(v);
    asm("mov.b64 %0, {%1, %1};" : "=l"(r) : "r"(u));
    return r;
}
__device__ __forceinline__ ull packab(float a, float b) {
    ull r; unsigned ua = __float_as_uint(a), ub = __float_as_uint(b);
    asm("mov.b64 %0, {%1, %2};" : "=l"(r) : "r"(ua), "r"(ub));
    return r;
}
__device__ __forceinline__ void fma2(ull &d, ull a, ull b) {
    asm("fma.rn.f32x2 %0, %1, %2, %0;" : "+l"(d) : "l"(a), "l"(b));
}
__device__ __forceinline__ float2 u2f(ull u) {
    float2 f; unsigned lo, hi;
    asm("mov.b64 {%0, %1}, %2;" : "=r"(lo), "=r"(hi) : "l"(u));
    f.x = __uint_as_float(lo); f.y = __uint_as_float(hi);
    return f;
}

// ---------------- K0: zero accumulators ----------------
__global__ void k_zero() {
    int i = blockIdx.x * blockDim.x + threadIdx.x;
    if (i < Bz*16*576) d_g[i] = 0.f;
    if (i < Bz*NC*NS) d_planeSum[i] = 0.f;
    if (i < Bz*NC*Cc) d_tok2[i] = 0.f;
    if (i < 2*Cc) d_stat[i] = 0.0;
}

// ---------------- K1: space planes + plane sums ----------------
// grid (12,12,16 planes), block 256
__global__ void __launch_bounds__(256) k_space(const float* __restrict__ cls,
                                               const float* __restrict__ Wc) {
    __shared__ float halo[18*18];
    __shared__ float wsm[63];
    __shared__ float bsum[8];
    int bc = blockIdx.z;
    int h0 = blockIdx.y * 16, w0 = blockIdx.x * 16;
    int tid = threadIdx.x;
    if (tid < 63) wsm[tid] = Wc[tid];
    if (tid < 8) bsum[tid] = 0.f;
    for (int idx = tid; idx < 324; idx += 256) {
        int r = idx / 18, cc = idx % 18;
        int gh = h0 - 1 + r, gw = w0 - 1 + cc;
        float v = 0.f;
        if (gh >= 0 && gh < Hh && gw >= 0 && gw < Ww)
            v = sigmf(cls[bc*HW + gh*Ww + gw]);
        halo[idx] = v;
    }
    __syncthreads();
    int py = tid >> 4, px = tid & 15;
    float vals[8];
    vals[0] = halo[(py+1)*18 + px + 1];
#pragma unroll
    for (int oc = 0; oc < 7; oc++) {
        float a = 0.f;
#pragma unroll
        for (int ky = 0; ky < 3; ky++)
#pragma unroll
            for (int kx = 0; kx < 3; kx++)
                a = fmaf(halo[(py+ky)*18 + px + kx], wsm[oc*9 + ky*3 + kx], a);
        vals[oc+1] = sigmf(a);
    }
    int pix = (h0 + py) * Ww + (w0 + px);
#pragma unroll
    for (int s = 0; s < 8; s++)
        d_space[(bc*8 + s)*HW + pix] = vals[s];
#pragma unroll
    for (int s = 0; s < 8; s++) {
        float r = vals[s];
#pragma unroll
        for (int off = 16; off > 0; off >>= 1)
            r += __shfl_xor_sync(0xffffffffu, r, off);
        if ((tid & 31) == 0) atomicAdd(&bsum[s], r);
    }
    __syncthreads();
    if (tid < 8) atomicAdd(&d_planeSum[bc*8 + tid], bsum[tid]);
}

// ---------------- K4 (moved early): F map ----------------
__global__ void k_F(const float* __restrict__ Wcv, const float* __restrict__ Wat,
                    const float* __restrict__ Wcb) {
    int idx = blockIdx.x * blockDim.x + threadIdx.x;
    if (idx >= Bz*NC*HW) return;
    int bc = idx / HW, hw = idx % HW;
    float p = d_space[bc*8*HW + hw];   // s=0 plane == class_prob
    float f = 0.f;
#pragma unroll
    for (int s = 0; s < 8; s++)
        f = fmaf(Wcb[s] * Wcv[s], sigmf(p * Wat[s]), f);
    d_F[idx] = f;
}

// ---------------- K2: g accumulation ----------------
// grid (36, 8), block (16,16): tx = 4-channel quad, ty = plane. 8 tiles/block.
// 288 blocks @ occ 2 -> single wave (296 slots), no tail.
__global__ void __launch_bounds__(256, 2) k_g(const float* __restrict__ x) {
    __shared__ float Ssm[16*180];                  // 16 planes, 10x18 halo
    __shared__ __align__(16) float Xsm[128*68];    // 128 px x 64 ch (pad 68)
    int b = blockIdx.y;
    int tx = threadIdx.x;   // 0..15: channels tx*4 .. tx*4+3
    int ty = threadIdx.y;   // 0..15: plane
    int tid = ty * 16 + tx;
    ull acc[9][2];
#pragma unroll
    for (int j = 0; j < 9; j++) { acc[j][0] = 0ull; acc[j][1] = 0ull; }

    for (int jt = 0; jt < 8; ++jt) {
        int t = blockIdx.x * 8 + jt;
        int h0 = (t / 12) * 8, wb = (t % 12) * 16;
        __syncthreads();
        for (int idx = tid; idx < 2880; idx += 256) {
            int sc = idx / 180, rem = idx % 180;
            int r = rem / 18, cc = rem % 18;
            int gh = h0 - 1 + r, gw = wb - 1 + cc;
            float v = 0.f;
            if (gh >= 0 && gh < Hh && gw >= 0 && gw < Ww)
                v = d_space[(b*16 + sc)*HW + gh*Ww + gw];
            Ssm[idx] = v;
        }
        {
            int p = tid >> 1, half = tid & 1;
            int prow = p >> 4, pcol = p & 15;
            const float* xp = x + (b*64 + half*32)*HW + (h0 + prow)*Ww + wb + pcol;
            float* xs = &Xsm[p*68 + half*32];
#pragma unroll 4
            for (int i = 0; i < 32; i += 2) {
                float2 v;
                v.x = xp[i * HW];
                v.y = xp[(i + 1) * HW];
                *(float2*)&xs[i] = v;
            }
        }
        __syncthreads();
        const float* Sp = &Ssm[ty * 180];
        for (int py = 0; py < 8; ++py) {
            const float* R0 = Sp + (py + 2) * 18;  // ky=0
            const float* R1 = Sp + (py + 1) * 18;  // ky=1
            const float* R2 = Sp + (py + 0) * 18;  // ky=2
            ull w0a = pack2(R0[0]), w0b = pack2(R0[1]), w0c = pack2(R0[2]);
            ull w1a = pack2(R1[0]), w1b = pack2(R1[1]), w1c = pack2(R1[2]);
            ull w2a = pack2(R2[0]), w2b = pack2(R2[1]), w2c = pack2(R2[2]);
#pragma unroll
            for (int px = 0; px < 16; ++px) {
                int p = py * 16 + px;
                ulonglong2 xa = *(const ulonglong2*)&Xsm[p*68 + tx*4];
                ull xv0 = xa.x, xv1 = xa.y;
                fma2(acc[0][0], w0c, xv0); fma2(acc[0][1], w0c, xv1);
                fma2(acc[1][0], w0b, xv0); fma2(acc[1][1], w0b, xv1);
                fma2(acc[2][0], w0a, xv0); fma2(acc[2][1], w0a, xv1);
                fma2(acc[3][0], w1c, xv0); fma2(acc[3][1], w1c, xv1);
                fma2(acc[4][0], w1b, xv0); fma2(acc[4][1], w1b, xv1);
                fma2(acc[5][0], w1a, xv0); fma2(acc[5][1], w1a, xv1);
                fma2(acc[6][0], w2c, xv0); fma2(acc[6][1], w2c, xv1);
                fma2(acc[7][0], w2b, xv0); fma2(acc[7][1], w2b, xv1);
                fma2(acc[8][0], w2a, xv0); fma2(acc[8][1], w2a, xv1);
                w0a = w0b; w0b = w0c;
                w1a = w1b; w1b = w1c;
                w2a = w2b; w2b = w2c;
                if (px < 15) {
                    w0c = pack2(R0[px + 3]);
                    w1c = pack2(R1[px + 3]);
                    w2c = pack2(R2[px + 3]);
                }
            }
        }
    }
    float* gb = &d_g[(b*16 + ty) * 576];
#pragma unroll
    for (int j = 0; j < 9; j++)
#pragma unroll
        for (int m = 0; m < 2; m++) {
            float2 f = u2f(acc[j][m]);
            int i0 = tx*4 + 2*m;
            atomicAdd(&gb[i0*9 + j],     f.x);
            atomicAdd(&gb[(i0+1)*9 + j], f.y);
        }
}

// ---------------- K3a: tok2 ----------------
// grid (16 chunk, 8 s), block 256
__global__ void __launch_bounds__(256) k_tok2(const float* __restrict__ Wx,
                                              const float* __restrict__ Wcs) {
    __shared__ float gsm[16*36];
    __shared__ float scl[16];
    int s = blockIdx.y, ck = blockIdx.x;   // ck: 36-float chunk of 576
    int tid = threadIdx.x;
    if (tid < 16) scl[tid] = Wcs[s] / d_planeSum[tid*8 + s];
    __syncthreads();
    for (int idx = tid; idx < 576; idx += 256) {
        int bc = idx / 36, e = idx % 36;
        int plane = (bc >> 1)*16 + (bc & 1)*8 + s;
        gsm[idx] = d_g[plane*576 + ck*36 + e] * scl[bc];
    }
    __syncthreads();
    int d = tid & 63, q = tid >> 6;
    const float4* w4 = (const float4*)(Wx + (s*64 + d)*576 + ck*36);
    float a0 = 0.f, a1 = 0.f, a2 = 0.f, a3 = 0.f;
    const float4* g0 = (const float4*)&gsm[(q*4 + 0)*36];
    const float4* g1 = (const float4*)&gsm[(q*4 + 1)*36];
    const float4* g2 = (const float4*)&gsm[(q*4 + 2)*36];
    const float4* g3 = (const float4*)&gsm[(q*4 + 3)*36];
#pragma unroll
    for (int t = 0; t < 9; t++) {
        float4 w = w4[t];
        float4 v;
        v = g0[t]; a0 = fmaf(w.x,v.x,fmaf(w.y,v.y,fmaf(w.z,v.z,fmaf(w.w,v.w,a0))));
        v = g1[t]; a1 = fmaf(w.x,v.x,fmaf(w.y,v.y,fmaf(w.z,v.z,fmaf(w.w,v.w,a1))));
        v = g2[t]; a2 = fmaf(w.x,v.x,fmaf(w.y,v.y,fmaf(w.z,v.z,fmaf(w.w,v.w,a2))));
        v = g3[t]; a3 = fmaf(w.x,v.x,fmaf(w.y,v.y,fmaf(w.z,v.z,fmaf(w.w,v.w,a3))));
    }
    atomicAdd(&d_tok2[(q*4 + 0)*64 + d], a0);
    atomicAdd(&d_tok2[(q*4 + 1)*64 + d], a1);
    atomicAdd(&d_tok2[(q*4 + 2)*64 + d], a2);
    atomicAdd(&d_tok2[(q*4 + 3)*64 + d], a3);
}

// ---------------- K3b: Weff ----------------
__global__ void __launch_bounds__(576) k_weff(const float* __restrict__ Ws) {
    __shared__ float t2[64];
    int bc = blockIdx.x;
    int tid = threadIdx.x;
    if (tid < 64) t2[tid] = d_tok2[bc*64 + tid];
    __syncthreads();
    int o = tid / 9, k = tid % 9;
    float a = 0.f;
#pragma unroll 8
    for (int d = 0; d < 64; d++)
        a = fmaf(t2[d], Ws[(o*64 + d)*9 + k], a);
    d_Weff[bc*576 + tid] = a;
}

// ---------------- K5: BN stats (sum, sumsq of y), 8 px/thread, f32x2 ----------------
// grid (36, 8), block 128; tile 16 rows x 64 cols
__global__ void __launch_bounds__(128) k_stats() {
    __shared__ float Fh[2*18*68];
    __shared__ ull wp[1152];
    int b = blockIdx.y, t = blockIdx.x;
    int h0 = (t / 3) * 16, w0 = (t % 3) * 64;
    int tid = threadIdx.x;
    for (int idx = tid; idx < 2*18*66; idx += 128) {
        int c = idx / (18*66), rem = idx % (18*66);
        int r = rem / 66, cc = rem % 66;
        int gh = h0 - 1 + r, gw = w0 - 1 + cc;
        float v = 0.f;
        if (gh >= 0 && gh < Hh && gw >= 0 && gw < Ww)
            v = d_F[(b*2 + c)*HW + gh*Ww + gw];
        Fh[c*1224 + r*68 + cc] = v;
    }
    for (int idx = tid; idx < 1152; idx += 128)
        wp[idx] = pack2(d_Weff[b*1152 + idx]);
    __syncthreads();
    int rowp = tid >> 3, tx = tid & 7, px0 = tx * 8;
    ull p2[2][3][9];
#pragma unroll
    for (int c = 0; c < 2; c++)
#pragma unroll
        for (int ky = 0; ky < 3; ky++) {
            const float* Fr = &Fh[c*1224 + (rowp + ky)*68 + px0];
            float prev = Fr[0];
#pragma unroll
            for (int tt = 0; tt < 9; tt++) {
                float cur = Fr[tt + 1];
                p2[c][ky][tt] = packab(prev, cur);
                prev = cur;
            }
        }
    for (int o = 0; o < 64; o++) {
        ull y0 = 0, y1 = 0, y2 = 0, y3 = 0;
#pragma unroll
        for (int c = 0; c < 2; c++)
#pragma unroll
            for (int kk = 0; kk < 9; kk++) {
                ull w = wp[(c*64 + o)*9 + kk];
                int ky = kk / 3, kx = kk % 3;
                fma2(y0, p2[c][ky][kx],     w);
                fma2(y1, p2[c][ky][2 + kx], w);
                fma2(y2, p2[c][ky][4 + kx], w);
                fma2(y3, p2[c][ky][6 + kx], w);
            }
        float2 f0 = u2f(y0), f1 = u2f(y1), f2 = u2f(y2), f3 = u2f(y3);
        float s = f0.x + f0.y + f1.x + f1.y + f2.x + f2.y + f3.x + f3.y;
        float q = f0.x*f0.x + f0.y*f0.y + f1.x*f1.x + f1.y*f1.y
                + f2.x*f2.x + f2.y*f2.y + f3.x*f3.x + f3.y*f3.y;
#pragma unroll
        for (int off = 16; off > 0; off >>= 1) {
            s += __shfl_xor_sync(0xffffffffu, s, off);
            q += __shfl_xor_sync(0xffffffffu, q, off);
        }
        if ((tid & 31) == 0) {
            atomicAdd(&d_stat[o], (double)s);
            atomicAdd(&d_stat[64 + o], (double)q);
        }
    }
}

// ---------------- K6: finalize BN ----------------
__global__ void k_finalize(const float* __restrict__ gamma,
                           const float* __restrict__ beta) {
    int o = threadIdx.x;
    double N = (double)(Bz * HW);
    double mean = d_stat[o] / N;
    double var = d_stat[64 + o] / N - mean * mean;
    float al = gamma[o] * rsqrtf((float)var + 1e-5f);
    d_alpha[o] = al;
    d_beta2[o] = beta[o] - (float)mean * al;
}

// ---------------- K7: output = x + relu(BN(y)), 8 px/thread, f32x2 ----------------
// grid (36, 8), block 128; tile 16 rows x 64 cols
__global__ void __launch_bounds__(128) k_out(const float* __restrict__ x,
                                             float* __restrict__ out) {
    __shared__ float Fh[2*18*68];
    __shared__ ull wp[1152];
    __shared__ float alsm[64], besm[64];
    int b = blockIdx.y, t = blockIdx.x;
    int h0 = (t / 3) * 16, w0 = (t % 3) * 64;
    int tid = threadIdx.x;
    for (int idx = tid; idx < 2*18*66; idx += 128) {
        int c = idx / (18*66), rem = idx % (18*66);
        int r = rem / 66, cc = rem % 66;
        int gh = h0 - 1 + r, gw = w0 - 1 + cc;
        float v = 0.f;
        if (gh >= 0 && gh < Hh && gw >= 0 && gw < Ww)
            v = d_F[(b*2 + c)*HW + gh*Ww + gw];
        Fh[c*1224 + r*68 + cc] = v;
    }
    for (int idx = tid; idx < 1152; idx += 128)
        wp[idx] = pack2(d_Weff[b*1152 + idx]);
    if (tid < 64) { alsm[tid] = d_alpha[tid]; besm[tid] = d_beta2[tid]; }
    __syncthreads();
    int rowp = tid >> 3, tx = tid & 7, px0 = tx * 8;
    ull p2[2][3][9];
#pragma unroll
    for (int c = 0; c < 2; c++)
#pragma unroll
        for (int ky = 0; ky < 3; ky++) {
            const float* Fr = &Fh[c*1224 + (rowp + ky)*68 + px0];
            float prev = Fr[0];
#pragma unroll
            for (int tt = 0; tt < 9; tt++) {
                float cur = Fr[tt + 1];
                p2[c][ky][tt] = packab(prev, cur);
                prev = cur;
            }
        }
    int pixbase = (h0 + rowp) * Ww + w0 + px0;
    for (int o = 0; o < 64; o++) {
        ull y0 = 0, y1 = 0, y2 = 0, y3 = 0;
#pragma unroll
        for (int c = 0; c < 2; c++)
#pragma unroll
            for (int kk = 0; kk < 9; kk++) {
                ull w = wp[(c*64 + o)*9 + kk];
                int ky = kk / 3, kx = kk % 3;
                fma2(y0, p2[c][ky][kx],     w);
                fma2(y1, p2[c][ky][2 + kx], w);
                fma2(y2, p2[c][ky][4 + kx], w);
                fma2(y3, p2[c][ky][6 + kx], w);
            }
        float al = alsm[o], be = besm[o];
        float2 f0 = u2f(y0), f1 = u2f(y1), f2 = u2f(y2), f3 = u2f(y3);
        long off = (long)(b*64 + o)*HW + pixbase;
        const float4* xq = (const float4*)(x + off);
        float4 xa = xq[0], xb = xq[1];
        float4 ra, rb;
        ra.x = xa.x + fmaxf(fmaf(al, f0.x, be), 0.f);
        ra.y = xa.y + fmaxf(fmaf(al, f0.y, be), 0.f);
        ra.z = xa.z + fmaxf(fmaf(al, f1.x, be), 0.f);
        ra.w = xa.w + fmaxf(fmaf(al, f1.y, be), 0.f);
        rb.x = xb.x + fmaxf(fmaf(al, f2.x, be), 0.f);
        rb.y = xb.y + fmaxf(fmaf(al, f2.y, be), 0.f);
        rb.z = xb.z + fmaxf(fmaf(al, f3.x, be), 0.f);
        rb.w = xb.w + fmaxf(fmaf(al, f3.y, be), 0.f);
        float4* oq = (float4*)(out + off);
        oq[0] = ra;
        oq[1] = rb;
    }
}

extern "C" void kernel_launch(void* const* d_in, const int* in_sizes, int n_in,
                              void* d_out, int out_size) {
    const float* x    = (const float*)d_in[0];
    const float* cls  = (const float*)d_in[1];
    const float* Wc   = (const float*)d_in[2];
    const float* Wx   = (const float*)d_in[3];
    const float* Wcs  = (const float*)d_in[4];
    const float* Wcv  = (const float*)d_in[5];
    const float* Wat  = (const float*)d_in[6];
    const float* Wcb  = (const float*)d_in[7];
    const float* Ws   = (const float*)d_in[8];
    const float* gam  = (const float*)d_in[9];
    const float* bet  = (const float*)d_in[10];
    float* out = (float*)d_out;

    // Order chosen so the ncu capture slot (launch index 3) lands on k_g.
    k_zero<<<288, 256>>>();                              // 0
    k_space<<<dim3(12,12,16), 256>>>(cls, Wc);           // 1
    k_F<<<(Bz*NC*HW + 255)/256, 256>>>(Wcv, Wat, Wcb);   // 2 (only needs d_space)
    k_g<<<dim3(36,8), dim3(16,16)>>>(x);                 // 3  <-- profiled
    k_tok2<<<dim3(16,8), 256>>>(Wx, Wcs);                // 4
    k_weff<<<16, 576>>>(Ws);                             // 5
    k_stats<<<dim3(36,8), 128>>>();                      // 6
    k_finalize<<<1, 64>>>(gam, bet);                     // 7
    k_out<<<dim3(36,8), 128>>>(x, out);                  // 8
}

// round 8
// speedup vs baseline: 2.0132x; 1.1368x over previous
#include <cuda_runtime.h>
#include <math.h>

#define Bz 8
#define NC 2
#define NS 8
#define Cc 64
#define Hh 192
#define Ww 192
#define HW (Hh*Ww)
#define SW 194
#define PS (SW*SW)          // padded plane size 194x194

typedef unsigned long long ull;

// ---- scratch (static __device__, no allocations) ----
__device__ float d_space[Bz*NC*NS*PS];   // PADDED sigmoid space planes [b*16+cs][(h+1)*194+(w+1)]
__device__ float d_planeSum[Bz*NC*NS];   // per-plane spatial sums
__device__ float d_g[Bz*16*576];         // [b][cs(16)][i*9+k]   (i-major)
__device__ float d_tok2[Bz*NC*Cc];       // [b][c][d]
__device__ float d_Weff[Bz*NC*Cc*9];     // [b][c][o][k]
__device__ float d_F[Bz*NC*HW];          // attention-combined scalar map
__device__ double d_stat[2*Cc];          // per-channel sum, sumsq of y
__device__ float d_alpha[Cc];
__device__ float d_beta2[Cc];

__device__ __forceinline__ float sigmf(float v) {
    return 1.0f / (1.0f + __expf(-v));
}

// ---- f32x2 packed helpers ----
__device__ __forceinline__ ull pack2(float v) {
    ull r; unsigned u = __float_as_uint(v);
    asm("mov.b64 %0, {%1, %1};" : "=l"(r) : "r"(u));
    return r;
}
__device__ __forceinline__ ull packab(float a, float b) {
    ull r; unsigned ua = __float_as_uint(a), ub = __float_as_uint(b);
    asm("mov.b64 %0, {%1, %2};" : "=l"(r) : "r"(ua), "r"(ub));
    return r;
}
__device__ __forceinline__ void fma2(ull &d, ull a, ull b) {
    asm("fma.rn.f32x2 %0, %1, %2, %0;" : "+l"(d) : "l"(a), "l"(b));
}
__device__ __forceinline__ float2 u2f(ull u) {
    float2 f; unsigned lo, hi;
    asm("mov.b64 {%0, %1}, %2;" : "=r"(lo), "=r"(hi) : "l"(u));
    f.x = __uint_as_float(lo); f.y = __uint_as_float(hi);
    return f;
}

// ---- cp.async helpers ----
__device__ __forceinline__ void cpa4(const float* dst_smem, const float* src) {
    unsigned d = (unsigned)__cvta_generic_to_shared(dst_smem);
    asm volatile("cp.async.ca.shared.global [%0], [%1], 4;" :: "r"(d), "l"(src));
}
#define CPA_COMMIT() asm volatile("cp.async.commit_group;" ::: "memory")
#define CPA_WAIT(N)  asm volatile("cp.async.wait_group %0;" :: "n"(N) : "memory")

// ---------------- K0: zero accumulators + d_space border ----------------
__global__ void k_zero() {
    int i = blockIdx.x * blockDim.x + threadIdx.x;
    if (i < Bz*16*576) d_g[i] = 0.f;
    if (i < Bz*NC*NS) d_planeSum[i] = 0.f;
    if (i < Bz*NC*Cc) d_tok2[i] = 0.f;
    if (i < 2*Cc) d_stat[i] = 0.0;
    // zero padded border of every d_space plane (772 elems/plane, 128 planes)
    if (i < 128*772) {
        int plane = i / 772, e = i % 772;
        int r, c;
        if (e < 194)      { r = 0;        c = e; }
        else if (e < 388) { r = 193;      c = e - 194; }
        else if (e < 580) { r = e - 388 + 1; c = 0; }
        else              { r = e - 580 + 1; c = 193; }
        d_space[plane*PS + r*SW + c] = 0.f;
    }
}

// ---------------- K1: space planes (padded write) + plane sums ----------------
// grid (12,12,16 planes), block 256
__global__ void __launch_bounds__(256) k_space(const float* __restrict__ cls,
                                               const float* __restrict__ Wc) {
    __shared__ float halo[18*18];
    __shared__ float wsm[63];
    __shared__ float bsum[8];
    int bc = blockIdx.z;
    int h0 = blockIdx.y * 16, w0 = blockIdx.x * 16;
    int tid = threadIdx.x;
    if (tid < 63) wsm[tid] = Wc[tid];
    if (tid < 8) bsum[tid] = 0.f;
    for (int idx = tid; idx < 324; idx += 256) {
        int r = idx / 18, cc = idx % 18;
        int gh = h0 - 1 + r, gw = w0 - 1 + cc;
        float v = 0.f;
        if (gh >= 0 && gh < Hh && gw >= 0 && gw < Ww)
            v = sigmf(cls[bc*HW + gh*Ww + gw]);
        halo[idx] = v;
    }
    __syncthreads();
    int py = tid >> 4, px = tid & 15;
    float vals[8];
    vals[0] = halo[(py+1)*18 + px + 1];
#pragma unroll
    for (int oc = 0; oc < 7; oc++) {
        float a = 0.f;
#pragma unroll
        for (int ky = 0; ky < 3; ky++)
#pragma unroll
            for (int kx = 0; kx < 3; kx++)
                a = fmaf(halo[(py+ky)*18 + px + kx], wsm[oc*9 + ky*3 + kx], a);
        vals[oc+1] = sigmf(a);
    }
    int pix = (h0 + py + 1) * SW + (w0 + px + 1);
#pragma unroll
    for (int s = 0; s < 8; s++)
        d_space[(bc*8 + s)*PS + pix] = vals[s];
#pragma unroll
    for (int s = 0; s < 8; s++) {
        float r = vals[s];
#pragma unroll
        for (int off = 16; off > 0; off >>= 1)
            r += __shfl_xor_sync(0xffffffffu, r, off);
        if ((tid & 31) == 0) atomicAdd(&bsum[s], r);
    }
    __syncthreads();
    if (tid < 8) atomicAdd(&d_planeSum[bc*8 + tid], bsum[tid]);
}

// ---------------- K4: F map (reads cls directly) ----------------
__global__ void k_F(const float* __restrict__ cls, const float* __restrict__ Wcv,
                    const float* __restrict__ Wat, const float* __restrict__ Wcb) {
    int idx = blockIdx.x * blockDim.x + threadIdx.x;
    if (idx >= Bz*NC*HW) return;
    float p = sigmf(cls[idx]);
    float f = 0.f;
#pragma unroll
    for (int s = 0; s < 8; s++)
        f = fmaf(Wcb[s] * Wcv[s], sigmf(p * Wat[s]), f);
    d_F[idx] = f;
}

// ---------------- K2: g accumulation (cp.async double-buffered) ----------------
// grid (18, 8), block (16,16): tx = 4-ch quad, ty = plane. 16 tiles (8x16 px) per block.
// Dynamic smem: 2 x (Ssm 2880 + Xsm 8704) floats = 92672 B.
__global__ void __launch_bounds__(256, 2) k_g(const float* __restrict__ x) {
    extern __shared__ __align__(16) float dyn[];
    float* Sb0 = dyn;
    float* Sb1 = dyn + 2880;
    float* Xb0 = dyn + 5760;
    float* Xb1 = dyn + 5760 + 8704;
    int b = blockIdx.y;
    int tx = threadIdx.x;   // 0..15: channels tx*4 .. tx*4+3
    int ty = threadIdx.y;   // 0..15: plane
    int tid = ty * 16 + tx;
    int p_ld = tid >> 1, half = tid & 1;
    int prow = p_ld >> 4, pcol = p_ld & 15;
    const float* xbase = x + (b*64 + half*32)*HW + prow*Ww + pcol;
    const float* spbase = d_space + b*16*PS;

    ull acc[9][2];
#pragma unroll
    for (int j = 0; j < 9; j++) { acc[j][0] = 0ull; acc[j][1] = 0ull; }

    // --- issue loads for a tile into a buffer ---
    auto issue = [&](int t, float* Sb, float* Xb) {
        int h0 = (t / 12) * 8, wb = (t % 12) * 16;
        // Ssm: padded reads, no bounds checks. 2880 elems.
        for (int idx = tid; idx < 2880; idx += 256) {
            int sc = idx / 180, rem = idx % 180;
            int r = rem / 18, cc = rem % 18;
            cpa4(Sb + idx, spbase + sc*PS + (h0 + r)*SW + (wb + cc));
        }
        // Xsm: 32 channels per thread-half, 4B each (strided src).
        const float* xp = xbase + h0*Ww + wb;
        float* xs = Xb + p_ld*68 + half*32;
#pragma unroll 8
        for (int i = 0; i < 32; i++)
            cpa4(xs + i, xp + i*HW);
    };

    issue(blockIdx.x * 16, Sb0, Xb0);
    CPA_COMMIT();

    for (int jt = 0; jt < 16; ++jt) {
        float* Sb = (jt & 1) ? Sb1 : Sb0;
        float* Xb = (jt & 1) ? Xb1 : Xb0;
        if (jt < 15) {
            issue(blockIdx.x * 16 + jt + 1, (jt & 1) ? Sb0 : Sb1, (jt & 1) ? Xb0 : Xb1);
            CPA_COMMIT();
            CPA_WAIT(1);
        } else {
            CPA_WAIT(0);
        }
        __syncthreads();
        const float* Sp = Sb + ty * 180;
        for (int py = 0; py < 8; ++py) {
            const float* R0 = Sp + (py + 2) * 18;  // ky=0
            const float* R1 = Sp + (py + 1) * 18;  // ky=1
            const float* R2 = Sp + (py + 0) * 18;  // ky=2
            ull w0a = pack2(R0[0]), w0b = pack2(R0[1]), w0c = pack2(R0[2]);
            ull w1a = pack2(R1[0]), w1b = pack2(R1[1]), w1c = pack2(R1[2]);
            ull w2a = pack2(R2[0]), w2b = pack2(R2[1]), w2c = pack2(R2[2]);
#pragma unroll
            for (int px = 0; px < 16; ++px) {
                int p = py * 16 + px;
                ulonglong2 xa = *(const ulonglong2*)&Xb[p*68 + tx*4];
                ull xv0 = xa.x, xv1 = xa.y;
                fma2(acc[0][0], w0c, xv0); fma2(acc[0][1], w0c, xv1);
                fma2(acc[1][0], w0b, xv0); fma2(acc[1][1], w0b, xv1);
                fma2(acc[2][0], w0a, xv0); fma2(acc[2][1], w0a, xv1);
                fma2(acc[3][0], w1c, xv0); fma2(acc[3][1], w1c, xv1);
                fma2(acc[4][0], w1b, xv0); fma2(acc[4][1], w1b, xv1);
                fma2(acc[5][0], w1a, xv0); fma2(acc[5][1], w1a, xv1);
                fma2(acc[6][0], w2c, xv0); fma2(acc[6][1], w2c, xv1);
                fma2(acc[7][0], w2b, xv0); fma2(acc[7][1], w2b, xv1);
                fma2(acc[8][0], w2a, xv0); fma2(acc[8][1], w2a, xv1);
                w0a = w0b; w0b = w0c;
                w1a = w1b; w1b = w1c;
                w2a = w2b; w2b = w2c;
                if (px < 15) {
                    w0c = pack2(R0[px + 3]);
                    w1c = pack2(R1[px + 3]);
                    w2c = pack2(R2[px + 3]);
                }
            }
        }
        __syncthreads();
    }
    float* gb = &d_g[(b*16 + ty) * 576];
#pragma unroll
    for (int j = 0; j < 9; j++)
#pragma unroll
        for (int m = 0; m < 2; m++) {
            float2 f = u2f(acc[j][m]);
            int i0 = tx*4 + 2*m;
            atomicAdd(&gb[i0*9 + j],     f.x);
            atomicAdd(&gb[(i0+1)*9 + j], f.y);
        }
}

// ---------------- K3a: tok2 ----------------
// grid (16 chunk, 8 s), block 256
__global__ void __launch_bounds__(256) k_tok2(const float* __restrict__ Wx,
                                              const float* __restrict__ Wcs) {
    __shared__ float gsm[16*36];
    __shared__ float scl[16];
    int s = blockIdx.y, ck = blockIdx.x;   // ck: 36-float chunk of 576
    int tid = threadIdx.x;
    if (tid < 16) scl[tid] = Wcs[s] / d_planeSum[tid*8 + s];
    __syncthreads();
    for (int idx = tid; idx < 576; idx += 256) {
        int bc = idx / 36, e = idx % 36;
        int plane = (bc >> 1)*16 + (bc & 1)*8 + s;
        gsm[idx] = d_g[plane*576 + ck*36 + e] * scl[bc];
    }
    __syncthreads();
    int d = tid & 63, q = tid >> 6;
    const float4* w4 = (const float4*)(Wx + (s*64 + d)*576 + ck*36);
    float a0 = 0.f, a1 = 0.f, a2 = 0.f, a3 = 0.f;
    const float4* g0 = (const float4*)&gsm[(q*4 + 0)*36];
    const float4* g1 = (const float4*)&gsm[(q*4 + 1)*36];
    const float4* g2 = (const float4*)&gsm[(q*4 + 2)*36];
    const float4* g3 = (const float4*)&gsm[(q*4 + 3)*36];
#pragma unroll
    for (int t = 0; t < 9; t++) {
        float4 w = w4[t];
        float4 v;
        v = g0[t]; a0 = fmaf(w.x,v.x,fmaf(w.y,v.y,fmaf(w.z,v.z,fmaf(w.w,v.w,a0))));
        v = g1[t]; a1 = fmaf(w.x,v.x,fmaf(w.y,v.y,fmaf(w.z,v.z,fmaf(w.w,v.w,a1))));
        v = g2[t]; a2 = fmaf(w.x,v.x,fmaf(w.y,v.y,fmaf(w.z,v.z,fmaf(w.w,v.w,a2))));
        v = g3[t]; a3 = fmaf(w.x,v.x,fmaf(w.y,v.y,fmaf(w.z,v.z,fmaf(w.w,v.w,a3))));
    }
    atomicAdd(&d_tok2[(q*4 + 0)*64 + d], a0);
    atomicAdd(&d_tok2[(q*4 + 1)*64 + d], a1);
    atomicAdd(&d_tok2[(q*4 + 2)*64 + d], a2);
    atomicAdd(&d_tok2[(q*4 + 3)*64 + d], a3);
}

// ---------------- K3b: Weff ----------------
__global__ void __launch_bounds__(576) k_weff(const float* __restrict__ Ws) {
    __shared__ float t2[64];
    int bc = blockIdx.x;
    int tid = threadIdx.x;
    if (tid < 64) t2[tid] = d_tok2[bc*64 + tid];
    __syncthreads();
    int o = tid / 9, k = tid % 9;
    float a = 0.f;
#pragma unroll 8
    for (int d = 0; d < 64; d++)
        a = fmaf(t2[d], Ws[(o*64 + d)*9 + k], a);
    d_Weff[bc*576 + tid] = a;
}

// ---------------- K5: BN stats, 8 px/thread, f32x2, smem-staged atomics ----------------
// grid (36, 8), block 128; tile 16 rows x 64 cols
__global__ void __launch_bounds__(128) k_stats() {
    __shared__ float Fh[2*18*68];
    __shared__ ull wp[1152];
    __shared__ float sred[512];   // [stat(2)][o(64)][warp(4)]
    int b = blockIdx.y, t = blockIdx.x;
    int h0 = (t / 3) * 16, w0 = (t % 3) * 64;
    int tid = threadIdx.x;
    for (int idx = tid; idx < 2*18*66; idx += 128) {
        int c = idx / (18*66), rem = idx % (18*66);
        int r = rem / 66, cc = rem % 66;
        int gh = h0 - 1 + r, gw = w0 - 1 + cc;
        float v = 0.f;
        if (gh >= 0 && gh < Hh && gw >= 0 && gw < Ww)
            v = d_F[(b*2 + c)*HW + gh*Ww + gw];
        Fh[c*1224 + r*68 + cc] = v;
    }
    for (int idx = tid; idx < 1152; idx += 128)
        wp[idx] = pack2(d_Weff[b*1152 + idx]);
    __syncthreads();
    int rowp = tid >> 3, tx = tid & 7, px0 = tx * 8;
    ull p2[2][3][9];
#pragma unroll
    for (int c = 0; c < 2; c++)
#pragma unroll
        for (int ky = 0; ky < 3; ky++) {
            const float* Fr = &Fh[c*1224 + (rowp + ky)*68 + px0];
            float prev = Fr[0];
#pragma unroll
            for (int tt = 0; tt < 9; tt++) {
                float cur = Fr[tt + 1];
                p2[c][ky][tt] = packab(prev, cur);
                prev = cur;
            }
        }
    for (int o = 0; o < 64; o++) {
        ull y0 = 0, y1 = 0, y2 = 0, y3 = 0;
#pragma unroll
        for (int c = 0; c < 2; c++)
#pragma unroll
            for (int kk = 0; kk < 9; kk++) {
                ull w = wp[(c*64 + o)*9 + kk];
                int ky = kk / 3, kx = kk % 3;
                fma2(y0, p2[c][ky][kx],     w);
                fma2(y1, p2[c][ky][2 + kx], w);
                fma2(y2, p2[c][ky][4 + kx], w);
                fma2(y3, p2[c][ky][6 + kx], w);
            }
        float2 f0 = u2f(y0), f1 = u2f(y1), f2 = u2f(y2), f3 = u2f(y3);
        float s = f0.x + f0.y + f1.x + f1.y + f2.x + f2.y + f3.x + f3.y;
        float q = f0.x*f0.x + f0.y*f0.y + f1.x*f1.x + f1.y*f1.y
                + f2.x*f2.x + f2.y*f2.y + f3.x*f3.x + f3.y*f3.y;
#pragma unroll
        for (int off = 16; off > 0; off >>= 1) {
            s += __shfl_xor_sync(0xffffffffu, s, off);
            q += __shfl_xor_sync(0xffffffffu, q, off);
        }
        if ((tid & 31) == 0) {
            sred[o*4 + (tid >> 5)]       = s;
            sred[256 + o*4 + (tid >> 5)] = q;
        }
    }
    __syncthreads();
    if (tid < 128) {
        int o = tid & 63, st = tid >> 6;
        const float* base = &sred[st*256 + o*4];
        double v = (double)base[0] + (double)base[1] + (double)base[2] + (double)base[3];
        atomicAdd(&d_stat[st*64 + o], v);
    }
}

// ---------------- K6: finalize BN ----------------
__global__ void k_finalize(const float* __restrict__ gamma,
                           const float* __restrict__ beta) {
    int o = threadIdx.x;
    double N = (double)(Bz * HW);
    double mean = d_stat[o] / N;
    double var = d_stat[64 + o] / N - mean * mean;
    float al = gamma[o] * rsqrtf((float)var + 1e-5f);
    d_alpha[o] = al;
    d_beta2[o] = beta[o] - (float)mean * al;
}

// ---------------- K7: output = x + relu(BN(y)), 8 px/thread, f32x2 ----------------
// grid (36, 8), block 128; tile 16 rows x 64 cols
__global__ void __launch_bounds__(128) k_out(const float* __restrict__ x,
                                             float* __restrict__ out) {
    __shared__ float Fh[2*18*68];
    __shared__ ull wp[1152];
    __shared__ float alsm[64], besm[64];
    int b = blockIdx.y, t = blockIdx.x;
    int h0 = (t / 3) * 16, w0 = (t % 3) * 64;
    int tid = threadIdx.x;
    for (int idx = tid; idx < 2*18*66; idx += 128) {
        int c = idx / (18*66), rem = idx % (18*66);
        int r = rem / 66, cc = rem % 66;
        int gh = h0 - 1 + r, gw = w0 - 1 + cc;
        float v = 0.f;
        if (gh >= 0 && gh < Hh && gw >= 0 && gw < Ww)
            v = d_F[(b*2 + c)*HW + gh*Ww + gw];
        Fh[c*1224 + r*68 + cc] = v;
    }
    for (int idx = tid; idx < 1152; idx += 128)
        wp[idx] = pack2(d_Weff[b*1152 + idx]);
    if (tid < 64) { alsm[tid] = d_alpha[tid]; besm[tid] = d_beta2[tid]; }
    __syncthreads();
    int rowp = tid >> 3, tx = tid & 7, px0 = tx * 8;
    ull p2[2][3][9];
#pragma unroll
    for (int c = 0; c < 2; c++)
#pragma unroll
        for (int ky = 0; ky < 3; ky++) {
            const float* Fr = &Fh[c*1224 + (rowp + ky)*68 + px0];
            float prev = Fr[0];
#pragma unroll
            for (int tt = 0; tt < 9; tt++) {
                float cur = Fr[tt + 1];
                p2[c][ky][tt] = packab(prev, cur);
                prev = cur;
            }
        }
    int pixbase = (h0 + rowp) * Ww + w0 + px0;
    for (int o = 0; o < 64; o++) {
        ull y0 = 0, y1 = 0, y2 = 0, y3 = 0;
#pragma unroll
        for (int c = 0; c < 2; c++)
#pragma unroll
            for (int kk = 0; kk < 9; kk++) {
                ull w = wp[(c*64 + o)*9 + kk];
                int ky = kk / 3, kx = kk % 3;
                fma2(y0, p2[c][ky][kx],     w);
                fma2(y1, p2[c][ky][2 + kx], w);
                fma2(y2, p2[c][ky][4 + kx], w);
                fma2(y3, p2[c][ky][6 + kx], w);
            }
        float al = alsm[o], be = besm[o];
        float2 f0 = u2f(y0), f1 = u2f(y1), f2 = u2f(y2), f3 = u2f(y3);
        long off = (long)(b*64 + o)*HW + pixbase;
        const float4* xq = (const float4*)(x + off);
        float4 xa = xq[0], xb = xq[1];
        float4 ra, rb;
        ra.x = xa.x + fmaxf(fmaf(al, f0.x, be), 0.f);
        ra.y = xa.y + fmaxf(fmaf(al, f0.y, be), 0.f);
        ra.z = xa.z + fmaxf(fmaf(al, f1.x, be), 0.f);
        ra.w = xa.w + fmaxf(fmaf(al, f1.y, be), 0.f);
        rb.x = xb.x + fmaxf(fmaf(al, f2.x, be), 0.f);
        rb.y = xb.y + fmaxf(fmaf(al, f2.y, be), 0.f);
        rb.z = xb.z + fmaxf(fmaf(al, f3.x, be), 0.f);
        rb.w = xb.w + fmaxf(fmaf(al, f3.y, be), 0.f);
        float4* oq = (float4*)(out + off);
        oq[0] = ra;
        oq[1] = rb;
    }
}

extern "C" void kernel_launch(void* const* d_in, const int* in_sizes, int n_in,
                              void* d_out, int out_size) {
    const float* x    = (const float*)d_in[0];
    const float* cls  = (const float*)d_in[1];
    const float* Wc   = (const float*)d_in[2];
    const float* Wx   = (const float*)d_in[3];
    const float* Wcs  = (const float*)d_in[4];
    const float* Wcv  = (const float*)d_in[5];
    const float* Wat  = (const float*)d_in[6];
    const float* Wcb  = (const float*)d_in[7];
    const float* Ws   = (const float*)d_in[8];
    const float* gam  = (const float*)d_in[9];
    const float* bet  = (const float*)d_in[10];
    float* out = (float*)d_out;

    const int KG_SMEM = (2*2880 + 2*8704) * 4;  // 92672 B
    cudaFuncSetAttribute(k_g, cudaFuncAttributeMaxDynamicSharedMemorySize, KG_SMEM);

    // Order keeps k_g at launch index 3 (the ncu capture slot).
    k_zero<<<400, 256>>>();                                   // 0
    k_space<<<dim3(12,12,16), 256>>>(cls, Wc);                // 1
    k_F<<<(Bz*NC*HW + 255)/256, 256>>>(cls, Wcv, Wat, Wcb);   // 2
    k_g<<<dim3(18,8), dim3(16,16), KG_SMEM>>>(x);             // 3  <-- profiled
    k_tok2<<<dim3(16,8), 256>>>(Wx, Wcs);                     // 4
    k_weff<<<16, 576>>>(Ws);                                  // 5
    k_stats<<<dim3(36,8), 128>>>();                           // 6
    k_finalize<<<1, 64>>>(gam, bet);                          // 7
    k_out<<<dim3(36,8), 128>>>(x, out);                       // 8
}